// round 14
// baseline (speedup 1.0000x reference)
#include <cuda_runtime.h>
#include <cuda_bf16.h>
#include <mma.h>
#include <math.h>
#include <stdint.h>
#include <string.h>

using namespace nvcuda;

#define NN     2048
#define NFEAT  512
#define NHID   128
#define NHEADS 4
#define NP     3
#define PH     (NP*NHEADS)
#define ALPHA  0.2f

// ---------------- device scratch ----------------
__device__ float g_m[NP * NN * (NHEADS*NHID)];
__device__ __align__(16) __nv_bfloat16 g_hThi[PH * NHID * NN];
__device__ __align__(16) __nv_bfloat16 g_hTlo[PH * NHID * NN];
__device__ __align__(16) __nv_bfloat16 g_xhi[NN * NFEAT];
__device__ __align__(16) __nv_bfloat16 g_xlo[NN * NFEAT];
__device__ __align__(16) __nv_bfloat16 g_Whi[PH * NFEAT * NHID];
__device__ __align__(16) __nv_bfloat16 g_Wlo[PH * NFEAT * NHID];
__device__ float4  g_sE4[PH * NN];     // (e^s, e^{as}, e^{-s}, -)
__device__ float2  g_dE2[PH * NN];     // (e^d, e^{ad})
__device__ uint32_t g_maskN[NP * NN * (NN/32)];
__device__ float g_scores[NP];

static __device__ __forceinline__ uint32_t b2u(__nv_bfloat162 h) {
    uint32_t u; memcpy(&u, &h, 4); return u;
}
static __device__ __forceinline__ uint32_t smem_u32(const void* p) {
    uint32_t a;
    asm("{ .reg .u64 t; cvta.to.shared.u64 t, %1; cvt.u32.u64 %0, t; }" : "=r"(a) : "l"(p));
    return a;
}
#define MBAR_INIT(a, c)  asm volatile("mbarrier.init.shared.b64 [%0], %1;" :: "r"((uint32_t)(a)), "r"((uint32_t)(c)) : "memory")
#define MBAR_ARRIVE(a)   asm volatile("mbarrier.arrive.shared.b64 _, [%0];" :: "r"((uint32_t)(a)) : "memory")
#define MBAR_WAIT(a, par) do { \
    uint32_t _m = (uint32_t)(a), _p = (uint32_t)(par), _d; \
    asm volatile("{\n\t.reg .pred p;\n\tmbarrier.try_wait.parity.acquire.cta.shared::cta.b64 p, [%1], %2;\n\tselp.b32 %0, 1, 0, p;\n\t}" \
                 : "=r"(_d) : "r"(_m), "r"(_p) : "memory"); \
    if (!_d) { \
        asm volatile("{\n\t.reg .pred P1;\n\tWL_%=:\n\tmbarrier.try_wait.parity.acquire.cta.shared::cta.b64 P1, [%0], %1, 0x989680;\n\t@P1 bra.uni WD_%=;\n\tbra.uni WL_%=;\n\tWD_%=:\n\t}" \
                     :: "r"(_m), "r"(_p) : "memory"); \
    } \
} while (0)
#define CP_ASYNC16(smem, gptr) \
    asm volatile("cp.async.cg.shared.global [%0], [%1], 16;" :: "r"((uint32_t)(smem)), "l"(gptr) : "memory")
#define CP_COMMIT()  asm volatile("cp.async.commit_group;" ::: "memory")
#define CP_WAIT0()   asm volatile("cp.async.wait_group 0;" ::: "memory")
#define CP_WAIT1()   asm volatile("cp.async.wait_group 1;" ::: "memory")

// ---------------- k0 ----------------
__global__ void k0_init() { if (threadIdx.x < NP) g_scores[threadIdx.x] = 0.f; }

// ---------------- k_prep: fused split + pack ----------
#define NXE (NN * NFEAT)
#define NWE (PH * NFEAT * NHID)
#define SPLIT_BLOCKS ((NXE + NWE + 255) / 256)
#define PACK_BLOCKS  (NP * NN * 64 / 8)
__global__ __launch_bounds__(256) void k_prep(const float* __restrict__ x,
                                              const float* __restrict__ Wn,
                                              const float* __restrict__ adjs) {
    {
        int g = blockIdx.x * 8 + (threadIdx.x >> 5);
        int lane = threadIdx.x & 31;
        float v = adjs[(size_t)g * 32 + lane];
        uint32_t b = __ballot_sync(0xffffffffu, v > 0.f);
        if (lane == 0) g_maskN[g] = b;
    }
    if (blockIdx.x < SPLIT_BLOCKS) {
        int i = blockIdx.x * 256 + threadIdx.x;
        if (i < NXE) {
            float v = x[i];
            __nv_bfloat16 h = __float2bfloat16_rn(v);
            g_xhi[i] = h;
            g_xlo[i] = __float2bfloat16_rn(v - __bfloat162float(h));
        }
        int j = i - NXE;
        if (j >= 0 && j < NWE) {
            float v = Wn[j];
            __nv_bfloat16 h = __float2bfloat16_rn(v);
            g_Whi[j] = h;
            g_Wlo[j] = __float2bfloat16_rn(v - __bfloat162float(h));
        }
    }
}

// ---------------- k1: 3-stage cp.async pipelined WMMA node GEMM (unchanged) ---
#define K1_LDA   72
#define K1_LDB   136
#define K1_LDC   132
#define K1_ST    71680
#define K1_OAL   18432
#define K1_OBH   36864
#define K1_OBL   54272
#define K1_OAN   215040
#define K1_ORS   216064
#define K1_ORD   217088
#define K1_SMEM_BYTES 218112

__global__ __launch_bounds__(256) void k1_node_wmma(const float* __restrict__ an) {
    extern __shared__ char sm[];
    uint32_t sbase = smem_u32(sm);
    float* csh   = (float*)(sm);
    float* a_sh  = (float*)(sm + K1_OAN);
    float* red_s = (float*)(sm + K1_ORS);
    float* red_d = (float*)(sm + K1_ORD);

    int ph   = blockIdx.y;
    int row0 = blockIdx.x * 128;
    int tid  = threadIdx.x;
    int warp = tid >> 5;
    int wr   = warp >> 1;
    int wc   = warp & 1;

    int rA = tid >> 1, hA = tid & 1;
    int rB = tid >> 2, qB = tid & 3;

    const char* xsrcH = (const char*)(g_xhi + (size_t)(row0 + rA) * NFEAT + hA * 32);
    const char* xsrcL = (const char*)(g_xlo + (size_t)(row0 + rA) * NFEAT + hA * 32);
    const char* wsrcH = (const char*)(g_Whi + (size_t)ph * NFEAT * NHID + (size_t)rB * NHID + qB * 32);
    const char* wsrcL = (const char*)(g_Wlo + (size_t)ph * NFEAT * NHID + (size_t)rB * NHID + qB * 32);
    uint32_t adstH = sbase + rA * (K1_LDA * 2) + hA * 64;
    uint32_t adstL = adstH + K1_OAL;
    uint32_t bdstH = sbase + K1_OBH + rB * (K1_LDB * 2) + qB * 64;
    uint32_t bdstL = bdstH + (K1_OBL - K1_OBH);

#define K1_ISSUE(c) do { \
    int _s = (c) % 3; uint32_t _sb = _s * K1_ST; size_t _ko = (size_t)(c) * 64; \
    const char* _xh = xsrcH + _ko * 2; const char* _xl = xsrcL + _ko * 2; \
    const char* _wh = wsrcH + _ko * NHID * 2; const char* _wl = wsrcL + _ko * NHID * 2; \
    CP_ASYNC16(adstH + _sb,      _xh);      CP_ASYNC16(adstH + _sb + 16, _xh + 16); \
    CP_ASYNC16(adstH + _sb + 32, _xh + 32); CP_ASYNC16(adstH + _sb + 48, _xh + 48); \
    CP_ASYNC16(adstL + _sb,      _xl);      CP_ASYNC16(adstL + _sb + 16, _xl + 16); \
    CP_ASYNC16(adstL + _sb + 32, _xl + 32); CP_ASYNC16(adstL + _sb + 48, _xl + 48); \
    CP_ASYNC16(bdstH + _sb,      _wh);      CP_ASYNC16(bdstH + _sb + 16, _wh + 16); \
    CP_ASYNC16(bdstH + _sb + 32, _wh + 32); CP_ASYNC16(bdstH + _sb + 48, _wh + 48); \
    CP_ASYNC16(bdstL + _sb,      _wl);      CP_ASYNC16(bdstL + _sb + 16, _wl + 16); \
    CP_ASYNC16(bdstL + _sb + 32, _wl + 32); CP_ASYNC16(bdstL + _sb + 48, _wl + 48); \
    CP_COMMIT(); \
} while (0)

    wmma::fragment<wmma::accumulator, 16, 16, 16, float> c[2][4];
#pragma unroll
    for (int i = 0; i < 2; i++)
#pragma unroll
        for (int j = 0; j < 4; j++) wmma::fill_fragment(c[i][j], 0.f);

    K1_ISSUE(0);
    K1_ISSUE(1);

    for (int ch = 0; ch < 8; ch++) {
        int s = ch % 3;
        if (ch < 7) { CP_WAIT1(); } else { CP_WAIT0(); }
        __syncthreads();
        if (ch + 2 < 8) K1_ISSUE(ch + 2);

        __nv_bfloat16* ash = (__nv_bfloat16*)(sm + s * K1_ST);
        __nv_bfloat16* asl = (__nv_bfloat16*)(sm + s * K1_ST + K1_OAL);
        __nv_bfloat16* bsh = (__nv_bfloat16*)(sm + s * K1_ST + K1_OBH);
        __nv_bfloat16* bsl = (__nv_bfloat16*)(sm + s * K1_ST + K1_OBL);

#pragma unroll
        for (int ks = 0; ks < 4; ks++) {
            int kk = ks * 16;
            wmma::fragment<wmma::matrix_a, 16, 16, 16, __nv_bfloat16, wmma::row_major> ah[2], al[2];
            wmma::fragment<wmma::matrix_b, 16, 16, 16, __nv_bfloat16, wmma::row_major> bh[4], bl[4];
#pragma unroll
            for (int i = 0; i < 2; i++) {
                wmma::load_matrix_sync(ah[i], ash + (wr * 32 + i * 16) * K1_LDA + kk, K1_LDA);
                wmma::load_matrix_sync(al[i], asl + (wr * 32 + i * 16) * K1_LDA + kk, K1_LDA);
            }
#pragma unroll
            for (int j = 0; j < 4; j++) {
                wmma::load_matrix_sync(bh[j], bsh + kk * K1_LDB + wc * 64 + j * 16, K1_LDB);
                wmma::load_matrix_sync(bl[j], bsl + kk * K1_LDB + wc * 64 + j * 16, K1_LDB);
            }
#pragma unroll
            for (int j = 0; j < 4; j++)
#pragma unroll
                for (int i = 0; i < 2; i++)
                    wmma::mma_sync(c[i][j], ah[i], bh[j], c[i][j]);
#pragma unroll
            for (int j = 0; j < 4; j++)
#pragma unroll
                for (int i = 0; i < 2; i++)
                    wmma::mma_sync(c[i][j], ah[i], bl[j], c[i][j]);
#pragma unroll
            for (int j = 0; j < 4; j++)
#pragma unroll
                for (int i = 0; i < 2; i++)
                    wmma::mma_sync(c[i][j], al[i], bh[j], c[i][j]);
        }
        __syncthreads();
    }

    a_sh[tid] = an[(size_t)ph * 2 * NHID + tid];
#pragma unroll
    for (int i = 0; i < 2; i++)
#pragma unroll
        for (int j = 0; j < 4; j++)
            wmma::store_matrix_sync(csh + (wr * 32 + i * 16) * K1_LDC + wc * 64 + j * 16,
                                    c[i][j], K1_LDC, wmma::mem_row_major);
    __syncthreads();

    {
        int r = tid & 127, hf = tid >> 7;
        float ps = 0.f, pd = 0.f;
        const float* row = csh + r * K1_LDC + hf * 64;
#pragma unroll
        for (int i = 0; i < 64; i++) {
            float v = row[i];
            ps += v * a_sh[hf * 64 + i];
            pd += v * a_sh[NHID + hf * 64 + i];
        }
        red_s[hf * 128 + r] = ps;
        red_d[hf * 128 + r] = pd;
    }

    {
        int d = tid & 127, hf = tid >> 7;
        __nv_bfloat16* dstH = g_hThi + ((size_t)ph * NHID + d) * NN + row0 + hf * 64;
        __nv_bfloat16* dstL = g_hTlo + ((size_t)ph * NHID + d) * NN + row0 + hf * 64;
#pragma unroll
        for (int i = 0; i < 64; i += 4) {
            float v0 = csh[(hf * 64 + i    ) * K1_LDC + d];
            float v1 = csh[(hf * 64 + i + 1) * K1_LDC + d];
            float v2 = csh[(hf * 64 + i + 2) * K1_LDC + d];
            float v3 = csh[(hf * 64 + i + 3) * K1_LDC + d];
            __nv_bfloat162 h01 = __float22bfloat162_rn(make_float2(v0, v1));
            __nv_bfloat162 h23 = __float22bfloat162_rn(make_float2(v2, v3));
            __nv_bfloat162 l01 = __float22bfloat162_rn(make_float2(v0 - __bfloat162float(h01.x),
                                                                   v1 - __bfloat162float(h01.y)));
            __nv_bfloat162 l23 = __float22bfloat162_rn(make_float2(v2 - __bfloat162float(h23.x),
                                                                   v3 - __bfloat162float(h23.y)));
            *(uint2*)(dstH + i) = make_uint2(b2u(h01), b2u(h23));
            *(uint2*)(dstL + i) = make_uint2(b2u(l01), b2u(l23));
        }
    }
    __syncthreads();
    if (tid < 128) {
        float s = red_s[tid] + red_s[128 + tid];
        float d = red_d[tid] + red_d[128 + tid];
        int idx = ph * NN + row0 + tid;
        g_sE4[idx] = make_float4(expf(s), expf(ALPHA * s), expf(-s), 0.f);
        g_dE2[idx] = make_float2(expf(d), expf(ALPHA * d));
    }
}

// ---------------- k3: 64-row tiles, 4+4 warps, 2 stages, 2 CTA/SM -------------
// stage (55296 B): AH@0 (64x72), AL@9216, BH@18432 (128x72), BL@36864.
// 2 stages = 110592. dE 2x512 @110592; rowsum 2x64 f32 @111616; mbar @112128.
// C tile (64x132 f32 = 33792) aliases stage 0.
#define LDA      72
#define LDC      132
#define NSTAGE   2
#define ST_STRIDE 55296
#define OFF_SAL  9216
#define OFF_SBH  18432
#define OFF_SBL  36864
#define OFF_DE   110592
#define OFF_ROW  111616
#define OFF_MBAR 112128
#define K3_SMEM_BYTES 112640

__global__ __launch_bounds__(256, 2) void k3_attn_wmma() {
    extern __shared__ char sm[];
    float*  csh  = (float*)(sm);
    float*  rsb  = (float*)(sm + OFF_ROW);
    uint32_t sbase = smem_u32(sm);
    uint32_t mbar = sbase + OFF_MBAR;

    int ph   = blockIdx.y;
    int p    = ph >> 2, head = ph & 3;
    int row0 = blockIdx.x * 64;
    int tid  = threadIdx.x;

    if (tid == 0) {
#pragma unroll
        for (int s = 0; s < NSTAGE; s++) {
            MBAR_INIT(mbar + s * 8, 128);        // full: 128 producers
            MBAR_INIT(mbar + 16 + s * 8, 128);   // empty: 128 consumers
        }
    }
    __syncthreads();

    wmma::fragment<wmma::accumulator, 16, 16, 16, float> c[2][4];

    if (tid < 128) {
        // ========== PRODUCER (4 warps): A-gen (2 thr/row) + B cp.async ==========
        int r    = tid >> 1;     // A row 0..63
        int half = tid & 1;      // m half
        float4 sE = g_sE4[ph * NN + row0 + r];
        const float Es_r = sE.x, Eas_r = sE.y, En_r = sE.z;
        float rs_local = 0.f;
        uint32_t phE[NSTAGE] = {0, 0};

        for (int chk = 0; chk < 32; chk++) {
            int s = chk & 1;
            int m0 = chk * 64;
            if (chk >= NSTAGE) { MBAR_WAIT(mbar + 16 + s * 8, phE[s]); phE[s] ^= 1; }

            {   // B tile: one d-row per thread (128 rows), 8x16B hi + 8x16B lo
                const char* srcH = (const char*)(g_hThi + ((size_t)ph * NHID + tid) * NN + m0);
                const char* srcL = (const char*)(g_hTlo + ((size_t)ph * NHID + tid) * NN + m0);
                uint32_t dstH = sbase + s * ST_STRIDE + OFF_SBH + tid * (LDA * 2);
                uint32_t dstL = sbase + s * ST_STRIDE + OFF_SBL + tid * (LDA * 2);
#pragma unroll
                for (int k = 0; k < 8; k++) {
                    CP_ASYNC16(dstH + k * 16, srcH + k * 16);
                    CP_ASYNC16(dstL + k * 16, srcL + k * 16);
                }
                CP_COMMIT();
            }
            float2* dEs = (float2*)(sm + OFF_DE + s * 512);
            if (tid < 64) dEs[tid] = g_dE2[ph * NN + m0 + tid];
            asm volatile("bar.sync 1, 128;" ::: "memory");   // dE visible to producers

            {   // A tile: row r, m in [m0+half*32, +32)
                __nv_bfloat16* ah_ = (__nv_bfloat16*)(sm + s * ST_STRIDE) + r * LDA + half * 32;
                __nv_bfloat16* al_ = (__nv_bfloat16*)(sm + s * ST_STRIDE + OFF_SAL) + r * LDA + half * 32;
                uint32_t mw = g_maskN[((size_t)p * NN + row0 + r) * 64 + chk * 2 + half];
#pragma unroll
                for (int g4 = 0; g4 < 4; g4++) {
                    float v[8];
#pragma unroll
                    for (int j = 0; j < 8; j++) {
                        float2 q = dEs[half * 32 + g4 * 8 + j];
                        float w = (q.x > En_r) ? (Es_r * q.x) : (Eas_r * q.y);
                        v[j] = ((mw >> (g4 * 8 + j)) & 1u) ? w : 0.f;
                        rs_local += v[j];
                    }
                    uint32_t hw[4], lw[4];
#pragma unroll
                    for (int jj = 0; jj < 4; jj++) {
                        __nv_bfloat162 h2 = __float22bfloat162_rn(make_float2(v[2*jj], v[2*jj+1]));
                        __nv_bfloat162 l2 = __float22bfloat162_rn(
                            make_float2(v[2*jj]   - __bfloat162float(h2.x),
                                        v[2*jj+1] - __bfloat162float(h2.y)));
                        hw[jj] = b2u(h2); lw[jj] = b2u(l2);
                    }
                    *(uint4*)(ah_ + g4 * 8) = make_uint4(hw[0], hw[1], hw[2], hw[3]);
                    *(uint4*)(al_ + g4 * 8) = make_uint4(lw[0], lw[1], lw[2], lw[3]);
                }
            }
            CP_WAIT0();
            MBAR_ARRIVE(mbar + s * 8);
        }
        rsb[half * 64 + r] = rs_local;
    } else {
        // ========== CONSUMER (4 warps, each 32x64 of the 64x128 C tile) ==========
        int cw = (tid >> 5) - 4;     // 0..3
        int wr = cw >> 1;            // 2 row groups of 32
        int wc = cw & 1;             // 2 col groups of 64
        uint32_t phF[NSTAGE] = {0, 0};

#pragma unroll
        for (int i = 0; i < 2; i++)
#pragma unroll
            for (int j = 0; j < 4; j++) wmma::fill_fragment(c[i][j], 0.f);

        for (int chk = 0; chk < 32; chk++) {
            int s = chk & 1;
            MBAR_WAIT(mbar + s * 8, phF[s]); phF[s] ^= 1;

            __nv_bfloat16* ash = (__nv_bfloat16*)(sm + s * ST_STRIDE);
            __nv_bfloat16* asl = (__nv_bfloat16*)(sm + s * ST_STRIDE + OFF_SAL);
            __nv_bfloat16* bsh = (__nv_bfloat16*)(sm + s * ST_STRIDE + OFF_SBH);
            __nv_bfloat16* bsl = (__nv_bfloat16*)(sm + s * ST_STRIDE + OFF_SBL);

#pragma unroll
            for (int ks = 0; ks < 4; ks++) {
                int kk = ks * 16;
                wmma::fragment<wmma::matrix_a, 16, 16, 16, __nv_bfloat16, wmma::row_major> ah[2], al[2];
#pragma unroll
                for (int i = 0; i < 2; i++) {
                    wmma::load_matrix_sync(ah[i], ash + (wr * 32 + i * 16) * LDA + kk, LDA);
                    wmma::load_matrix_sync(al[i], asl + (wr * 32 + i * 16) * LDA + kk, LDA);
                }
#pragma unroll
                for (int j = 0; j < 4; j++) {
                    wmma::fragment<wmma::matrix_b, 16, 16, 16, __nv_bfloat16, wmma::col_major> bh, bl;
                    wmma::load_matrix_sync(bh, bsh + (wc * 64 + j * 16) * LDA + kk, LDA);
                    wmma::load_matrix_sync(bl, bsl + (wc * 64 + j * 16) * LDA + kk, LDA);
#pragma unroll
                    for (int i = 0; i < 2; i++) {
                        wmma::mma_sync(c[i][j], ah[i], bh, c[i][j]);
                        wmma::mma_sync(c[i][j], ah[i], bl, c[i][j]);
                        wmma::mma_sync(c[i][j], al[i], bh, c[i][j]);
                    }
                }
            }
            MBAR_ARRIVE(mbar + 16 + s * 8);
        }
    }

    __syncthreads();   // stages dead, rowsums visible
    if (tid >= 128) {
        int cw = (tid >> 5) - 4;
        int wr = cw >> 1, wc = cw & 1;
#pragma unroll
        for (int i = 0; i < 2; i++)
#pragma unroll
            for (int j = 0; j < 4; j++)
                wmma::store_matrix_sync(csh + (wr * 32 + i * 16) * LDC + wc * 64 + j * 16,
                                        c[i][j], LDC, wmma::mem_row_major);
    }
    __syncthreads();

    if (tid < 128) {
        int rr  = tid & 63;
        int chf = tid >> 6;
        float rsum = rsb[rr] + rsb[64 + rr];
        float inv = (rsum > 0.f) ? (1.f / rsum) : 0.f;
        const float* src = csh + rr * LDC + chf * 64;
        float* dst = g_m + ((size_t)p * NN + row0 + rr) * (NHEADS * NHID) + head * NHID + chf * 64;
#pragma unroll
        for (int cc = 0; cc < 64; cc += 4) {
            float f0 = src[cc]   * inv;
            float f1 = src[cc+1] * inv;
            float f2 = src[cc+2] * inv;
            float f3 = src[cc+3] * inv;
            f0 = (f0 > 0.f) ? f0 : expm1f(f0);
            f1 = (f1 > 0.f) ? f1 : expm1f(f1);
            f2 = (f2 > 0.f) ? f2 : expm1f(f2);
            f3 = (f3 > 0.f) ? f3 : expm1f(f3);
            *(float4*)(dst + cc) = make_float4(f0, f1, f2, f3);
        }
    }
}

// ---------------- k4: semantic scores ----------------
__global__ __launch_bounds__(256) void k4_sem(const float* __restrict__ Wsem,
                                              const float* __restrict__ bsem,
                                              const float* __restrict__ qsem) {
    __shared__ float msh[32][65];
    __shared__ float wsh[64 * 128];
    __shared__ float red[8];
    int row0 = blockIdx.x * 32;
    int pidx = row0 / NN;
    int tid = threadIdx.x;
    int rg = tid >> 5;
    int cg = tid & 31;

    float acc[4][4];
#pragma unroll
    for (int r = 0; r < 4; r++)
#pragma unroll
        for (int c = 0; c < 4; c++) acc[r][c] = 0.f;

    for (int k0 = 0; k0 < 512; k0 += 64) {
        for (int i = tid; i < 32 * 64; i += 256)
            msh[i >> 6][i & 63] = g_m[(size_t)(row0 + (i >> 6)) * 512 + k0 + (i & 63)];
        for (int i = tid * 4; i < 64 * 128; i += 1024)
            *(float4*)&wsh[i] = *(const float4*)&Wsem[(size_t)k0 * 128 + i];
        __syncthreads();
#pragma unroll
        for (int k = 0; k < 64; k++) {
            float mv[4];
#pragma unroll
            for (int r = 0; r < 4; r++) mv[r] = msh[rg * 4 + r][k];
            float4 wv = *(float4*)&wsh[k * 128 + cg * 4];
            float wva[4] = {wv.x, wv.y, wv.z, wv.w};
#pragma unroll
            for (int r = 0; r < 4; r++)
#pragma unroll
                for (int c = 0; c < 4; c++) acc[r][c] += mv[r] * wva[c];
        }
        __syncthreads();
    }
    float part = 0.f;
#pragma unroll
    for (int c = 0; c < 4; c++) {
        int col = cg * 4 + c;
        float b = bsem[col], q = qsem[col];
#pragma unroll
        for (int r = 0; r < 4; r++)
            part += tanhf(acc[r][c] + b) * q;
    }
#pragma unroll
    for (int off = 16; off; off >>= 1)
        part += __shfl_xor_sync(0xffffffffu, part, off);
    if ((tid & 31) == 0) red[tid >> 5] = part;
    __syncthreads();
    if (tid == 0) {
        float tot = 0.f;
#pragma unroll
        for (int i = 0; i < 8; i++) tot += red[i];
        atomicAdd(&g_scores[pidx], tot);
    }
}

// ---------------- k6 ----------------
__global__ __launch_bounds__(256) void k6_out(float* __restrict__ out) {
    __shared__ float w[NP];
    if (threadIdx.x == 0) {
        float s0 = g_scores[0] * (1.f / NN);
        float s1 = g_scores[1] * (1.f / NN);
        float s2 = g_scores[2] * (1.f / NN);
        float mx = fmaxf(s0, fmaxf(s1, s2));
        float e0 = expf(s0 - mx), e1 = expf(s1 - mx), e2 = expf(s2 - mx);
        float inv = 1.f / (e0 + e1 + e2);
        w[0] = e0 * inv; w[1] = e1 * inv; w[2] = e2 * inv;
    }
    __syncthreads();
    size_t i = (size_t)blockIdx.x * blockDim.x + threadIdx.x;
    const size_t stride = (size_t)NN * 512;
    out[i] = w[0] * g_m[i] + w[1] * g_m[stride + i] + w[2] * g_m[2 * stride + i];
}

// ---------------- launch ----------------
extern "C" void kernel_launch(void* const* d_in, const int* in_sizes, int n_in,
                              void* d_out, int out_size) {
    const float* x    = (const float*)d_in[0];
    const float* adjs = (const float*)d_in[1];
    const float* Wn   = (const float*)d_in[2];
    const float* an   = (const float*)d_in[3];
    const float* Wsem = (const float*)d_in[4];
    const float* bsem = (const float*)d_in[5];
    const float* qsem = (const float*)d_in[6];
    float* out = (float*)d_out;

    cudaFuncSetAttribute(k3_attn_wmma, cudaFuncAttributeMaxDynamicSharedMemorySize, K3_SMEM_BYTES);
    cudaFuncSetAttribute(k1_node_wmma, cudaFuncAttributeMaxDynamicSharedMemorySize, K1_SMEM_BYTES);

    k0_init<<<1, 32>>>();
    k_prep<<<PACK_BLOCKS, 256>>>(x, Wn, adjs);
    k1_node_wmma<<<dim3(NN / 128, PH), 256, K1_SMEM_BYTES>>>(an);
    k3_attn_wmma<<<dim3(NN / 64, PH), 256, K3_SMEM_BYTES>>>();   // profiled slot
    k4_sem<<<(NP * NN) / 32, 256>>>(Wsem, bsem, qsem);
    k6_out<<<(NN * 512) / 256, 256>>>(out);
}

// round 15
// speedup vs baseline: 1.0007x; 1.0007x over previous
#include <cuda_runtime.h>
#include <cuda_bf16.h>
#include <mma.h>
#include <math.h>
#include <stdint.h>
#include <string.h>

using namespace nvcuda;

#define NN     2048
#define NFEAT  512
#define NHID   128
#define NHEADS 4
#define NP     3
#define PH     (NP*NHEADS)
#define ALPHA  0.2f

// ---------------- device scratch ----------------
__device__ float g_m[NP * NN * (NHEADS*NHID)];
__device__ __align__(16) __nv_bfloat16 g_hThi[PH * NHID * NN];
__device__ __align__(16) __nv_bfloat16 g_hTlo[PH * NHID * NN];
__device__ __align__(16) __nv_bfloat16 g_xhi[NN * NFEAT];
__device__ __align__(16) __nv_bfloat16 g_xlo[NN * NFEAT];
__device__ __align__(16) __nv_bfloat16 g_Whi[PH * NFEAT * NHID];
__device__ __align__(16) __nv_bfloat16 g_Wlo[PH * NFEAT * NHID];
__device__ float4  g_sE4[PH * NN];     // (e^s, e^{as}, e^{-s}, -)
__device__ float2  g_dE2[PH * NN];     // (e^d, e^{ad})
__device__ uint32_t g_maskN[NP * NN * (NN/32)];
__device__ float g_scores[NP];

static __device__ __forceinline__ uint32_t b2u(__nv_bfloat162 h) {
    uint32_t u; memcpy(&u, &h, 4); return u;
}
static __device__ __forceinline__ uint32_t smem_u32(const void* p) {
    uint32_t a;
    asm("{ .reg .u64 t; cvta.to.shared.u64 t, %1; cvt.u32.u64 %0, t; }" : "=r"(a) : "l"(p));
    return a;
}
#define MBAR_INIT(a, c)  asm volatile("mbarrier.init.shared.b64 [%0], %1;" :: "r"((uint32_t)(a)), "r"((uint32_t)(c)) : "memory")
#define MBAR_ARRIVE(a)   asm volatile("mbarrier.arrive.shared.b64 _, [%0];" :: "r"((uint32_t)(a)) : "memory")
#define MBAR_WAIT(a, par) do { \
    uint32_t _m = (uint32_t)(a), _p = (uint32_t)(par), _d; \
    asm volatile("{\n\t.reg .pred p;\n\tmbarrier.try_wait.parity.acquire.cta.shared::cta.b64 p, [%1], %2;\n\tselp.b32 %0, 1, 0, p;\n\t}" \
                 : "=r"(_d) : "r"(_m), "r"(_p) : "memory"); \
    if (!_d) { \
        asm volatile("{\n\t.reg .pred P1;\n\tWL_%=:\n\tmbarrier.try_wait.parity.acquire.cta.shared::cta.b64 P1, [%0], %1, 0x989680;\n\t@P1 bra.uni WD_%=;\n\tbra.uni WL_%=;\n\tWD_%=:\n\t}" \
                     :: "r"(_m), "r"(_p) : "memory"); \
    } \
} while (0)
#define CP_ASYNC16(smem, gptr) \
    asm volatile("cp.async.cg.shared.global [%0], [%1], 16;" :: "r"((uint32_t)(smem)), "l"(gptr) : "memory")
#define CP_COMMIT()  asm volatile("cp.async.commit_group;" ::: "memory")
#define CP_WAIT0()   asm volatile("cp.async.wait_group 0;" ::: "memory")
#define CP_WAIT1()   asm volatile("cp.async.wait_group 1;" ::: "memory")

// ---------------- k0 ----------------
__global__ void k0_init() { if (threadIdx.x < NP) g_scores[threadIdx.x] = 0.f; }

// ---------------- k_prep: fused split + pack ----------
#define NXE (NN * NFEAT)
#define NWE (PH * NFEAT * NHID)
#define SPLIT_BLOCKS ((NXE + NWE + 255) / 256)
#define PACK_BLOCKS  (NP * NN * 64 / 8)
__global__ __launch_bounds__(256) void k_prep(const float* __restrict__ x,
                                              const float* __restrict__ Wn,
                                              const float* __restrict__ adjs) {
    {
        int g = blockIdx.x * 8 + (threadIdx.x >> 5);
        int lane = threadIdx.x & 31;
        float v = adjs[(size_t)g * 32 + lane];
        uint32_t b = __ballot_sync(0xffffffffu, v > 0.f);
        if (lane == 0) g_maskN[g] = b;
    }
    if (blockIdx.x < SPLIT_BLOCKS) {
        int i = blockIdx.x * 256 + threadIdx.x;
        if (i < NXE) {
            float v = x[i];
            __nv_bfloat16 h = __float2bfloat16_rn(v);
            g_xhi[i] = h;
            g_xlo[i] = __float2bfloat16_rn(v - __bfloat162float(h));
        }
        int j = i - NXE;
        if (j >= 0 && j < NWE) {
            float v = Wn[j];
            __nv_bfloat16 h = __float2bfloat16_rn(v);
            g_Whi[j] = h;
            g_Wlo[j] = __float2bfloat16_rn(v - __bfloat162float(h));
        }
    }
}

// ---------------- k1: 2-stage K=32 pipelined WMMA node GEMM, 2 CTA/SM ---------
// stage (37888 B): AH@0 (128x40 bf16), AL@10240, BH@20480 (32x136), BL@29184.
// 2 stages = 75776. a_sh@75776, red_s@76800, red_d@77824. C (128x132 f32) aliases.
#define K1_LDA   40
#define K1_LDB   136
#define K1_LDC   132
#define K1_ST    37888
#define K1_OAL   10240
#define K1_OBH   20480
#define K1_OBL   29184
#define K1_OAN   75776
#define K1_ORS   76800
#define K1_ORD   77824
#define K1_SMEM_BYTES 78848

__global__ __launch_bounds__(256, 2) void k1_node_wmma(const float* __restrict__ an) {
    extern __shared__ char sm[];
    uint32_t sbase = smem_u32(sm);
    float* csh   = (float*)(sm);
    float* a_sh  = (float*)(sm + K1_OAN);
    float* red_s = (float*)(sm + K1_ORS);
    float* red_d = (float*)(sm + K1_ORD);

    int ph   = blockIdx.y;
    int row0 = blockIdx.x * 128;
    int tid  = threadIdx.x;
    int warp = tid >> 5;
    int wr   = warp >> 1;
    int wc   = warp & 1;

    int rA = tid >> 1, hA = tid & 1;    // A: row, 16-elem half
    int rB = tid >> 3, qB = tid & 7;    // B: k-row (32), 16-elem eighth

    const char* xsrcH = (const char*)(g_xhi + (size_t)(row0 + rA) * NFEAT + hA * 16);
    const char* xsrcL = (const char*)(g_xlo + (size_t)(row0 + rA) * NFEAT + hA * 16);
    const char* wsrcH = (const char*)(g_Whi + (size_t)ph * NFEAT * NHID + (size_t)rB * NHID + qB * 16);
    const char* wsrcL = (const char*)(g_Wlo + (size_t)ph * NFEAT * NHID + (size_t)rB * NHID + qB * 16);
    uint32_t adstH = sbase + rA * (K1_LDA * 2) + hA * 32;
    uint32_t adstL = adstH + K1_OAL;
    uint32_t bdstH = sbase + K1_OBH + rB * (K1_LDB * 2) + qB * 32;
    uint32_t bdstL = bdstH + (K1_OBL - K1_OBH);

#define K1_ISSUE(c) do { \
    uint32_t _sb = ((c) & 1) * K1_ST; size_t _ko = (size_t)(c) * 32; \
    const char* _xh = xsrcH + _ko * 2; const char* _xl = xsrcL + _ko * 2; \
    const char* _wh = wsrcH + _ko * NHID * 2; const char* _wl = wsrcL + _ko * NHID * 2; \
    CP_ASYNC16(adstH + _sb,      _xh); CP_ASYNC16(adstH + _sb + 16, _xh + 16); \
    CP_ASYNC16(adstL + _sb,      _xl); CP_ASYNC16(adstL + _sb + 16, _xl + 16); \
    CP_ASYNC16(bdstH + _sb,      _wh); CP_ASYNC16(bdstH + _sb + 16, _wh + 16); \
    CP_ASYNC16(bdstL + _sb,      _wl); CP_ASYNC16(bdstL + _sb + 16, _wl + 16); \
    CP_COMMIT(); \
} while (0)

    wmma::fragment<wmma::accumulator, 16, 16, 16, float> c[2][4];
#pragma unroll
    for (int i = 0; i < 2; i++)
#pragma unroll
        for (int j = 0; j < 4; j++) wmma::fill_fragment(c[i][j], 0.f);

    K1_ISSUE(0);

    for (int ch = 0; ch < 16; ch++) {
        int s = ch & 1;
        if (ch + 1 < 16) { K1_ISSUE(ch + 1); CP_WAIT1(); } else { CP_WAIT0(); }
        __syncthreads();

        __nv_bfloat16* ash = (__nv_bfloat16*)(sm + s * K1_ST);
        __nv_bfloat16* asl = (__nv_bfloat16*)(sm + s * K1_ST + K1_OAL);
        __nv_bfloat16* bsh = (__nv_bfloat16*)(sm + s * K1_ST + K1_OBH);
        __nv_bfloat16* bsl = (__nv_bfloat16*)(sm + s * K1_ST + K1_OBL);

#pragma unroll
        for (int ks = 0; ks < 2; ks++) {
            int kk = ks * 16;
            wmma::fragment<wmma::matrix_a, 16, 16, 16, __nv_bfloat16, wmma::row_major> ah[2], al[2];
            wmma::fragment<wmma::matrix_b, 16, 16, 16, __nv_bfloat16, wmma::row_major> bh[4], bl[4];
#pragma unroll
            for (int i = 0; i < 2; i++) {
                wmma::load_matrix_sync(ah[i], ash + (wr * 32 + i * 16) * K1_LDA + kk, K1_LDA);
                wmma::load_matrix_sync(al[i], asl + (wr * 32 + i * 16) * K1_LDA + kk, K1_LDA);
            }
#pragma unroll
            for (int j = 0; j < 4; j++) {
                wmma::load_matrix_sync(bh[j], bsh + kk * K1_LDB + wc * 64 + j * 16, K1_LDB);
                wmma::load_matrix_sync(bl[j], bsl + kk * K1_LDB + wc * 64 + j * 16, K1_LDB);
            }
#pragma unroll
            for (int j = 0; j < 4; j++)
#pragma unroll
                for (int i = 0; i < 2; i++)
                    wmma::mma_sync(c[i][j], ah[i], bh[j], c[i][j]);
#pragma unroll
            for (int j = 0; j < 4; j++)
#pragma unroll
                for (int i = 0; i < 2; i++)
                    wmma::mma_sync(c[i][j], ah[i], bl[j], c[i][j]);
#pragma unroll
            for (int j = 0; j < 4; j++)
#pragma unroll
                for (int i = 0; i < 2; i++)
                    wmma::mma_sync(c[i][j], al[i], bh[j], c[i][j]);
        }
        __syncthreads();
    }

    a_sh[tid] = an[(size_t)ph * 2 * NHID + tid];
#pragma unroll
    for (int i = 0; i < 2; i++)
#pragma unroll
        for (int j = 0; j < 4; j++)
            wmma::store_matrix_sync(csh + (wr * 32 + i * 16) * K1_LDC + wc * 64 + j * 16,
                                    c[i][j], K1_LDC, wmma::mem_row_major);
    __syncthreads();

    {
        int r = tid & 127, hf = tid >> 7;
        float ps = 0.f, pd = 0.f;
        const float* row = csh + r * K1_LDC + hf * 64;
#pragma unroll
        for (int i = 0; i < 64; i++) {
            float v = row[i];
            ps += v * a_sh[hf * 64 + i];
            pd += v * a_sh[NHID + hf * 64 + i];
        }
        red_s[hf * 128 + r] = ps;
        red_d[hf * 128 + r] = pd;
    }

    {
        int d = tid & 127, hf = tid >> 7;
        __nv_bfloat16* dstH = g_hThi + ((size_t)ph * NHID + d) * NN + row0 + hf * 64;
        __nv_bfloat16* dstL = g_hTlo + ((size_t)ph * NHID + d) * NN + row0 + hf * 64;
#pragma unroll
        for (int i = 0; i < 64; i += 4) {
            float v0 = csh[(hf * 64 + i    ) * K1_LDC + d];
            float v1 = csh[(hf * 64 + i + 1) * K1_LDC + d];
            float v2 = csh[(hf * 64 + i + 2) * K1_LDC + d];
            float v3 = csh[(hf * 64 + i + 3) * K1_LDC + d];
            __nv_bfloat162 h01 = __float22bfloat162_rn(make_float2(v0, v1));
            __nv_bfloat162 h23 = __float22bfloat162_rn(make_float2(v2, v3));
            __nv_bfloat162 l01 = __float22bfloat162_rn(make_float2(v0 - __bfloat162float(h01.x),
                                                                   v1 - __bfloat162float(h01.y)));
            __nv_bfloat162 l23 = __float22bfloat162_rn(make_float2(v2 - __bfloat162float(h23.x),
                                                                   v3 - __bfloat162float(h23.y)));
            *(uint2*)(dstH + i) = make_uint2(b2u(h01), b2u(h23));
            *(uint2*)(dstL + i) = make_uint2(b2u(l01), b2u(l23));
        }
    }
    __syncthreads();
    if (tid < 128) {
        float s = red_s[tid] + red_s[128 + tid];
        float d = red_d[tid] + red_d[128 + tid];
        int idx = ph * NN + row0 + tid;
        g_sE4[idx] = make_float4(expf(s), expf(ALPHA * s), expf(-s), 0.f);
        g_dE2[idx] = make_float2(expf(d), expf(ALPHA * d));
    }
}

// ---------------- k3: producers=pure A-gen (direct dE LDG); consumers own B ----
#define LDA      72
#define LDC      132
#define NSTAGE   2
#define ST_STRIDE 55296
#define OFF_SAL  9216
#define OFF_SBH  18432
#define OFF_SBL  36864
#define OFF_ROW  110592
#define OFF_MBAR 111104
#define K3_SMEM_BYTES 111616

__global__ __launch_bounds__(256, 2) void k3_attn_wmma() {
    extern __shared__ char sm[];
    float*  csh  = (float*)(sm);
    float*  rsb  = (float*)(sm + OFF_ROW);
    uint32_t sbase = smem_u32(sm);
    uint32_t mbar = sbase + OFF_MBAR;

    int ph   = blockIdx.y;
    int p    = ph >> 2, head = ph & 3;
    int row0 = blockIdx.x * 64;
    int tid  = threadIdx.x;

    if (tid == 0) {
#pragma unroll
        for (int s = 0; s < NSTAGE; s++) {
            MBAR_INIT(mbar + s * 8, 128);        // full: 128 producers
            MBAR_INIT(mbar + 16 + s * 8, 128);   // empty: 128 consumers
        }
    }
    __syncthreads();

    wmma::fragment<wmma::accumulator, 16, 16, 16, float> c[2][4];

    if (tid < 128) {
        // ========== PRODUCER (4 warps): pure A-gen, dE via direct LDG ==========
        int r    = tid >> 1;
        int half = tid & 1;
        float4 sE = g_sE4[ph * NN + row0 + r];
        const float Es_r = sE.x, Eas_r = sE.y, En_r = sE.z;
        float rs_local = 0.f;
        uint32_t phE[NSTAGE] = {0, 0};
        const float2* dEg = g_dE2 + ph * NN;

        for (int chk = 0; chk < 32; chk++) {
            int s = chk & 1;
            int m0 = chk * 64;
            if (chk >= NSTAGE) { MBAR_WAIT(mbar + 16 + s * 8, phE[s]); phE[s] ^= 1; }

            __nv_bfloat16* ah_ = (__nv_bfloat16*)(sm + s * ST_STRIDE) + r * LDA + half * 32;
            __nv_bfloat16* al_ = (__nv_bfloat16*)(sm + s * ST_STRIDE + OFF_SAL) + r * LDA + half * 32;
            uint32_t mw = g_maskN[((size_t)p * NN + row0 + r) * 64 + chk * 2 + half];
            const float2* dEc = dEg + m0 + half * 32;
#pragma unroll
            for (int g4 = 0; g4 < 4; g4++) {
                float2 q[8];
#pragma unroll
                for (int j = 0; j < 8; j++) q[j] = dEc[g4 * 8 + j];   // L1-broadcast
                float v[8];
#pragma unroll
                for (int j = 0; j < 8; j++) {
                    float w = (q[j].x > En_r) ? (Es_r * q[j].x) : (Eas_r * q[j].y);
                    v[j] = ((mw >> (g4 * 8 + j)) & 1u) ? w : 0.f;
                    rs_local += v[j];
                }
                uint32_t hw[4], lw[4];
#pragma unroll
                for (int jj = 0; jj < 4; jj++) {
                    __nv_bfloat162 h2 = __float22bfloat162_rn(make_float2(v[2*jj], v[2*jj+1]));
                    __nv_bfloat162 l2 = __float22bfloat162_rn(
                        make_float2(v[2*jj]   - __bfloat162float(h2.x),
                                    v[2*jj+1] - __bfloat162float(h2.y)));
                    hw[jj] = b2u(h2); lw[jj] = b2u(l2);
                }
                *(uint4*)(ah_ + g4 * 8) = make_uint4(hw[0], hw[1], hw[2], hw[3]);
                *(uint4*)(al_ + g4 * 8) = make_uint4(lw[0], lw[1], lw[2], lw[3]);
            }
            MBAR_ARRIVE(mbar + s * 8);
        }
        rsb[half * 64 + r] = rs_local;
    } else {
        // ========== CONSUMER (4 warps): MMA + own B cp.async pipeline ==========
        int idx = tid - 128;         // B row d = idx (0..127)
        int cw = (tid >> 5) - 4;
        int wr = cw >> 1;
        int wc = cw & 1;
        uint32_t phF[NSTAGE] = {0, 0};

        const char* bsrcH = (const char*)(g_hThi + ((size_t)ph * NHID + idx) * NN);
        const char* bsrcL = (const char*)(g_hTlo + ((size_t)ph * NHID + idx) * NN);
        uint32_t bdH = sbase + OFF_SBH + idx * (LDA * 2);
        uint32_t bdL = sbase + OFF_SBL + idx * (LDA * 2);

#define K3_BISSUE(c) do { \
    uint32_t _sb = ((c) & 1) * ST_STRIDE; size_t _mo = (size_t)(c) * 64 * 2; \
    const char* _sH = bsrcH + _mo; const char* _sL = bsrcL + _mo; \
    CP_ASYNC16(bdH + _sb,       _sH);      CP_ASYNC16(bdH + _sb + 16,  _sH + 16); \
    CP_ASYNC16(bdH + _sb + 32,  _sH + 32); CP_ASYNC16(bdH + _sb + 48,  _sH + 48); \
    CP_ASYNC16(bdH + _sb + 64,  _sH + 64); CP_ASYNC16(bdH + _sb + 80,  _sH + 80); \
    CP_ASYNC16(bdH + _sb + 96,  _sH + 96); CP_ASYNC16(bdH + _sb + 112, _sH + 112); \
    CP_ASYNC16(bdL + _sb,       _sL);      CP_ASYNC16(bdL + _sb + 16,  _sL + 16); \
    CP_ASYNC16(bdL + _sb + 32,  _sL + 32); CP_ASYNC16(bdL + _sb + 48,  _sL + 48); \
    CP_ASYNC16(bdL + _sb + 64,  _sL + 64); CP_ASYNC16(bdL + _sb + 80,  _sL + 80); \
    CP_ASYNC16(bdL + _sb + 96,  _sL + 96); CP_ASYNC16(bdL + _sb + 112, _sL + 112); \
    CP_COMMIT(); \
} while (0)

        K3_BISSUE(0);
        K3_BISSUE(1);

#pragma unroll
        for (int i = 0; i < 2; i++)
#pragma unroll
            for (int j = 0; j < 4; j++) wmma::fill_fragment(c[i][j], 0.f);

        for (int chk = 0; chk < 32; chk++) {
            int s = chk & 1;
            MBAR_WAIT(mbar + s * 8, phF[s]); phF[s] ^= 1;   // A ready
            if (chk < 31) { CP_WAIT1(); } else { CP_WAIT0(); }  // own B(chk) landed
            asm volatile("bar.sync 2, 128;" ::: "memory");      // all consumers' B visible

            __nv_bfloat16* ash = (__nv_bfloat16*)(sm + s * ST_STRIDE);
            __nv_bfloat16* asl = (__nv_bfloat16*)(sm + s * ST_STRIDE + OFF_SAL);
            __nv_bfloat16* bsh = (__nv_bfloat16*)(sm + s * ST_STRIDE + OFF_SBH);
            __nv_bfloat16* bsl = (__nv_bfloat16*)(sm + s * ST_STRIDE + OFF_SBL);

#pragma unroll
            for (int ks = 0; ks < 4; ks++) {
                int kk = ks * 16;
                wmma::fragment<wmma::matrix_a, 16, 16, 16, __nv_bfloat16, wmma::row_major> ah[2], al[2];
#pragma unroll
                for (int i = 0; i < 2; i++) {
                    wmma::load_matrix_sync(ah[i], ash + (wr * 32 + i * 16) * LDA + kk, LDA);
                    wmma::load_matrix_sync(al[i], asl + (wr * 32 + i * 16) * LDA + kk, LDA);
                }
#pragma unroll
                for (int j = 0; j < 4; j++) {
                    wmma::fragment<wmma::matrix_b, 16, 16, 16, __nv_bfloat16, wmma::col_major> bh, bl;
                    wmma::load_matrix_sync(bh, bsh + (wc * 64 + j * 16) * LDA + kk, LDA);
                    wmma::load_matrix_sync(bl, bsl + (wc * 64 + j * 16) * LDA + kk, LDA);
#pragma unroll
                    for (int i = 0; i < 2; i++) {
                        wmma::mma_sync(c[i][j], ah[i], bh, c[i][j]);
                        wmma::mma_sync(c[i][j], ah[i], bl, c[i][j]);
                        wmma::mma_sync(c[i][j], al[i], bh, c[i][j]);
                    }
                }
            }
            asm volatile("bar.sync 2, 128;" ::: "memory");   // all consumers done with stage
            MBAR_ARRIVE(mbar + 16 + s * 8);                  // release A region to producers
            if (chk + 2 < 32) K3_BISSUE(chk + 2);            // refill B region
        }
    }

    __syncthreads();   // stages dead, rowsums visible
    if (tid >= 128) {
        int cw = (tid >> 5) - 4;
        int wr = cw >> 1, wc = cw & 1;
#pragma unroll
        for (int i = 0; i < 2; i++)
#pragma unroll
            for (int j = 0; j < 4; j++)
                wmma::store_matrix_sync(csh + (wr * 32 + i * 16) * LDC + wc * 64 + j * 16,
                                        c[i][j], LDC, wmma::mem_row_major);
    }
    __syncthreads();

    if (tid < 128) {
        int rr  = tid & 63;
        int chf = tid >> 6;
        float rsum = rsb[rr] + rsb[64 + rr];
        float inv = (rsum > 0.f) ? (1.f / rsum) : 0.f;
        const float* src = csh + rr * LDC + chf * 64;
        float* dst = g_m + ((size_t)p * NN + row0 + rr) * (NHEADS * NHID) + head * NHID + chf * 64;
#pragma unroll
        for (int cc = 0; cc < 64; cc += 4) {
            float f0 = src[cc]   * inv;
            float f1 = src[cc+1] * inv;
            float f2 = src[cc+2] * inv;
            float f3 = src[cc+3] * inv;
            f0 = (f0 > 0.f) ? f0 : expm1f(f0);
            f1 = (f1 > 0.f) ? f1 : expm1f(f1);
            f2 = (f2 > 0.f) ? f2 : expm1f(f2);
            f3 = (f3 > 0.f) ? f3 : expm1f(f3);
            *(float4*)(dst + cc) = make_float4(f0, f1, f2, f3);
        }
    }
}

// ---------------- k4: semantic scores ----------------
__global__ __launch_bounds__(256) void k4_sem(const float* __restrict__ Wsem,
                                              const float* __restrict__ bsem,
                                              const float* __restrict__ qsem) {
    __shared__ float msh[32][65];
    __shared__ float wsh[64 * 128];
    __shared__ float red[8];
    int row0 = blockIdx.x * 32;
    int pidx = row0 / NN;
    int tid = threadIdx.x;
    int rg = tid >> 5;
    int cg = tid & 31;

    float acc[4][4];
#pragma unroll
    for (int r = 0; r < 4; r++)
#pragma unroll
        for (int c = 0; c < 4; c++) acc[r][c] = 0.f;

    for (int k0 = 0; k0 < 512; k0 += 64) {
        for (int i = tid; i < 32 * 64; i += 256)
            msh[i >> 6][i & 63] = g_m[(size_t)(row0 + (i >> 6)) * 512 + k0 + (i & 63)];
        for (int i = tid * 4; i < 64 * 128; i += 1024)
            *(float4*)&wsh[i] = *(const float4*)&Wsem[(size_t)k0 * 128 + i];
        __syncthreads();
#pragma unroll
        for (int k = 0; k < 64; k++) {
            float mv[4];
#pragma unroll
            for (int r = 0; r < 4; r++) mv[r] = msh[rg * 4 + r][k];
            float4 wv = *(float4*)&wsh[k * 128 + cg * 4];
            float wva[4] = {wv.x, wv.y, wv.z, wv.w};
#pragma unroll
            for (int r = 0; r < 4; r++)
#pragma unroll
                for (int c = 0; c < 4; c++) acc[r][c] += mv[r] * wva[c];
        }
        __syncthreads();
    }
    float part = 0.f;
#pragma unroll
    for (int c = 0; c < 4; c++) {
        int col = cg * 4 + c;
        float b = bsem[col], q = qsem[col];
#pragma unroll
        for (int r = 0; r < 4; r++)
            part += tanhf(acc[r][c] + b) * q;
    }
#pragma unroll
    for (int off = 16; off; off >>= 1)
        part += __shfl_xor_sync(0xffffffffu, part, off);
    if ((tid & 31) == 0) red[tid >> 5] = part;
    __syncthreads();
    if (tid == 0) {
        float tot = 0.f;
#pragma unroll
        for (int i = 0; i < 8; i++) tot += red[i];
        atomicAdd(&g_scores[pidx], tot);
    }
}

// ---------------- k6 ----------------
__global__ __launch_bounds__(256) void k6_out(float* __restrict__ out) {
    __shared__ float w[NP];
    if (threadIdx.x == 0) {
        float s0 = g_scores[0] * (1.f / NN);
        float s1 = g_scores[1] * (1.f / NN);
        float s2 = g_scores[2] * (1.f / NN);
        float mx = fmaxf(s0, fmaxf(s1, s2));
        float e0 = expf(s0 - mx), e1 = expf(s1 - mx), e2 = expf(s2 - mx);
        float inv = 1.f / (e0 + e1 + e2);
        w[0] = e0 * inv; w[1] = e1 * inv; w[2] = e2 * inv;
    }
    __syncthreads();
    size_t i = (size_t)blockIdx.x * blockDim.x + threadIdx.x;
    const size_t stride = (size_t)NN * 512;
    out[i] = w[0] * g_m[i] + w[1] * g_m[stride + i] + w[2] * g_m[2 * stride + i];
}

// ---------------- launch ----------------
extern "C" void kernel_launch(void* const* d_in, const int* in_sizes, int n_in,
                              void* d_out, int out_size) {
    const float* x    = (const float*)d_in[0];
    const float* adjs = (const float*)d_in[1];
    const float* Wn   = (const float*)d_in[2];
    const float* an   = (const float*)d_in[3];
    const float* Wsem = (const float*)d_in[4];
    const float* bsem = (const float*)d_in[5];
    const float* qsem = (const float*)d_in[6];
    float* out = (float*)d_out;

    cudaFuncSetAttribute(k3_attn_wmma, cudaFuncAttributeMaxDynamicSharedMemorySize, K3_SMEM_BYTES);
    cudaFuncSetAttribute(k1_node_wmma, cudaFuncAttributeMaxDynamicSharedMemorySize, K1_SMEM_BYTES);

    k0_init<<<1, 32>>>();
    k_prep<<<PACK_BLOCKS, 256>>>(x, Wn, adjs);
    k1_node_wmma<<<dim3(NN / 128, PH), 256, K1_SMEM_BYTES>>>(an);
    k3_attn_wmma<<<dim3(NN / 64, PH), 256, K3_SMEM_BYTES>>>();   // profiled slot
    k4_sem<<<(NP * NN) / 32, 256>>>(Wsem, bsem, qsem);
    k6_out<<<(NN * 512) / 256, 256>>>(out);
}

// round 16
// speedup vs baseline: 1.1893x; 1.1884x over previous
#include <cuda_runtime.h>
#include <cuda_bf16.h>
#include <cuda_fp16.h>
#include <mma.h>
#include <math.h>
#include <stdint.h>
#include <string.h>

using namespace nvcuda;

#define NN     2048
#define NFEAT  512
#define NHID   128
#define NHEADS 4
#define NP     3
#define PH     (NP*NHEADS)
#define ALPHA  0.2f

// ---------------- device scratch ----------------
__device__ float g_m[NP * NN * (NHEADS*NHID)];
__device__ __align__(16) __half g_hThi[PH * NHID * NN];   // hT fp16 hi
__device__ __align__(16) __half g_hTlo[PH * NHID * NN];   // hT fp16 lo
__device__ __align__(16) __nv_bfloat16 g_xhi[NN * NFEAT];
__device__ __align__(16) __nv_bfloat16 g_xlo[NN * NFEAT];
__device__ __align__(16) __nv_bfloat16 g_Whi[PH * NFEAT * NHID];
__device__ __align__(16) __nv_bfloat16 g_Wlo[PH * NFEAT * NHID];
__device__ float4  g_sE4[PH * NN];     // (e^s, e^{as}, e^{-s}, s)
__device__ float2  g_dE2[PH * NN];     // (e^d, e^{ad})
__device__ float   g_maxd[PH];
__device__ uint32_t g_maskN[NP * NN * (NN/32)];
__device__ float g_scores[NP];

static __device__ __forceinline__ uint32_t b2u(__nv_bfloat162 h) {
    uint32_t u; memcpy(&u, &h, 4); return u;
}
static __device__ __forceinline__ uint32_t h2u(__half2 h) {
    uint32_t u; memcpy(&u, &h, 4); return u;
}
static __device__ __forceinline__ uint32_t smem_u32(const void* p) {
    uint32_t a;
    asm("{ .reg .u64 t; cvta.to.shared.u64 t, %1; cvt.u32.u64 %0, t; }" : "=r"(a) : "l"(p));
    return a;
}
static __device__ __forceinline__ void atomicMaxFloat(float* addr, float val) {
    int* ia = (int*)addr;
    int old = *ia;
    while (val > __int_as_float(old)) {
        int assumed = old;
        old = atomicCAS(ia, assumed, __float_as_int(val));
        if (old == assumed) break;
    }
}
#define MBAR_INIT(a, c)  asm volatile("mbarrier.init.shared.b64 [%0], %1;" :: "r"((uint32_t)(a)), "r"((uint32_t)(c)) : "memory")
#define MBAR_ARRIVE(a)   asm volatile("mbarrier.arrive.shared.b64 _, [%0];" :: "r"((uint32_t)(a)) : "memory")
#define MBAR_WAIT(a, par) do { \
    uint32_t _m = (uint32_t)(a), _p = (uint32_t)(par), _d; \
    asm volatile("{\n\t.reg .pred p;\n\tmbarrier.try_wait.parity.acquire.cta.shared::cta.b64 p, [%1], %2;\n\tselp.b32 %0, 1, 0, p;\n\t}" \
                 : "=r"(_d) : "r"(_m), "r"(_p) : "memory"); \
    if (!_d) { \
        asm volatile("{\n\t.reg .pred P1;\n\tWL_%=:\n\tmbarrier.try_wait.parity.acquire.cta.shared::cta.b64 P1, [%0], %1, 0x989680;\n\t@P1 bra.uni WD_%=;\n\tbra.uni WL_%=;\n\tWD_%=:\n\t}" \
                     :: "r"(_m), "r"(_p) : "memory"); \
    } \
} while (0)
#define CP_ASYNC16(smem, gptr) \
    asm volatile("cp.async.cg.shared.global [%0], [%1], 16;" :: "r"((uint32_t)(smem)), "l"(gptr) : "memory")
#define CP_COMMIT()  asm volatile("cp.async.commit_group;" ::: "memory")
#define CP_WAIT0()   asm volatile("cp.async.wait_group 0;" ::: "memory")
#define CP_WAIT1()   asm volatile("cp.async.wait_group 1;" ::: "memory")

// ---------------- k0 ----------------
__global__ void k0_init() {
    if (threadIdx.x < NP) g_scores[threadIdx.x] = 0.f;
    if (threadIdx.x < PH) g_maxd[threadIdx.x] = -1e30f;
}

// ---------------- k_prep: fused split + pack ----------
#define NXE (NN * NFEAT)
#define NWE (PH * NFEAT * NHID)
#define SPLIT_BLOCKS ((NXE + NWE + 255) / 256)
#define PACK_BLOCKS  (NP * NN * 64 / 8)
__global__ __launch_bounds__(256) void k_prep(const float* __restrict__ x,
                                              const float* __restrict__ Wn,
                                              const float* __restrict__ adjs) {
    {
        int g = blockIdx.x * 8 + (threadIdx.x >> 5);
        int lane = threadIdx.x & 31;
        float v = adjs[(size_t)g * 32 + lane];
        uint32_t b = __ballot_sync(0xffffffffu, v > 0.f);
        if (lane == 0) g_maskN[g] = b;
    }
    if (blockIdx.x < SPLIT_BLOCKS) {
        int i = blockIdx.x * 256 + threadIdx.x;
        if (i < NXE) {
            float v = x[i];
            __nv_bfloat16 h = __float2bfloat16_rn(v);
            g_xhi[i] = h;
            g_xlo[i] = __float2bfloat16_rn(v - __bfloat162float(h));
        }
        int j = i - NXE;
        if (j >= 0 && j < NWE) {
            float v = Wn[j];
            __nv_bfloat16 h = __float2bfloat16_rn(v);
            g_Whi[j] = h;
            g_Wlo[j] = __float2bfloat16_rn(v - __bfloat162float(h));
        }
    }
}

// ---------------- k1: 2-stage K=32 pipelined WMMA node GEMM, 2 CTA/SM ---------
#define K1_LDA   40
#define K1_LDB   136
#define K1_LDC   132
#define K1_ST    37888
#define K1_OAL   10240
#define K1_OBH   20480
#define K1_OBL   29184
#define K1_OAN   75776
#define K1_ORS   76800
#define K1_ORD   77824
#define K1_SMEM_BYTES 78848

__global__ __launch_bounds__(256, 2) void k1_node_wmma(const float* __restrict__ an) {
    extern __shared__ char sm[];
    uint32_t sbase = smem_u32(sm);
    float* csh   = (float*)(sm);
    float* a_sh  = (float*)(sm + K1_OAN);
    float* red_s = (float*)(sm + K1_ORS);
    float* red_d = (float*)(sm + K1_ORD);

    int ph   = blockIdx.y;
    int row0 = blockIdx.x * 128;
    int tid  = threadIdx.x;
    int warp = tid >> 5;
    int wr   = warp >> 1;
    int wc   = warp & 1;

    int rA = tid >> 1, hA = tid & 1;
    int rB = tid >> 3, qB = tid & 7;

    const char* xsrcH = (const char*)(g_xhi + (size_t)(row0 + rA) * NFEAT + hA * 16);
    const char* xsrcL = (const char*)(g_xlo + (size_t)(row0 + rA) * NFEAT + hA * 16);
    const char* wsrcH = (const char*)(g_Whi + (size_t)ph * NFEAT * NHID + (size_t)rB * NHID + qB * 16);
    const char* wsrcL = (const char*)(g_Wlo + (size_t)ph * NFEAT * NHID + (size_t)rB * NHID + qB * 16);
    uint32_t adstH = sbase + rA * (K1_LDA * 2) + hA * 32;
    uint32_t adstL = adstH + K1_OAL;
    uint32_t bdstH = sbase + K1_OBH + rB * (K1_LDB * 2) + qB * 32;
    uint32_t bdstL = bdstH + (K1_OBL - K1_OBH);

#define K1_ISSUE(c) do { \
    uint32_t _sb = ((c) & 1) * K1_ST; size_t _ko = (size_t)(c) * 32; \
    const char* _xh = xsrcH + _ko * 2; const char* _xl = xsrcL + _ko * 2; \
    const char* _wh = wsrcH + _ko * NHID * 2; const char* _wl = wsrcL + _ko * NHID * 2; \
    CP_ASYNC16(adstH + _sb,      _xh); CP_ASYNC16(adstH + _sb + 16, _xh + 16); \
    CP_ASYNC16(adstL + _sb,      _xl); CP_ASYNC16(adstL + _sb + 16, _xl + 16); \
    CP_ASYNC16(bdstH + _sb,      _wh); CP_ASYNC16(bdstH + _sb + 16, _wh + 16); \
    CP_ASYNC16(bdstL + _sb,      _wl); CP_ASYNC16(bdstL + _sb + 16, _wl + 16); \
    CP_COMMIT(); \
} while (0)

    wmma::fragment<wmma::accumulator, 16, 16, 16, float> c[2][4];
#pragma unroll
    for (int i = 0; i < 2; i++)
#pragma unroll
        for (int j = 0; j < 4; j++) wmma::fill_fragment(c[i][j], 0.f);

    K1_ISSUE(0);

    for (int ch = 0; ch < 16; ch++) {
        int s = ch & 1;
        if (ch + 1 < 16) { K1_ISSUE(ch + 1); CP_WAIT1(); } else { CP_WAIT0(); }
        __syncthreads();

        __nv_bfloat16* ash = (__nv_bfloat16*)(sm + s * K1_ST);
        __nv_bfloat16* asl = (__nv_bfloat16*)(sm + s * K1_ST + K1_OAL);
        __nv_bfloat16* bsh = (__nv_bfloat16*)(sm + s * K1_ST + K1_OBH);
        __nv_bfloat16* bsl = (__nv_bfloat16*)(sm + s * K1_ST + K1_OBL);

#pragma unroll
        for (int ks = 0; ks < 2; ks++) {
            int kk = ks * 16;
            wmma::fragment<wmma::matrix_a, 16, 16, 16, __nv_bfloat16, wmma::row_major> ah[2], al[2];
            wmma::fragment<wmma::matrix_b, 16, 16, 16, __nv_bfloat16, wmma::row_major> bh[4], bl[4];
#pragma unroll
            for (int i = 0; i < 2; i++) {
                wmma::load_matrix_sync(ah[i], ash + (wr * 32 + i * 16) * K1_LDA + kk, K1_LDA);
                wmma::load_matrix_sync(al[i], asl + (wr * 32 + i * 16) * K1_LDA + kk, K1_LDA);
            }
#pragma unroll
            for (int j = 0; j < 4; j++) {
                wmma::load_matrix_sync(bh[j], bsh + kk * K1_LDB + wc * 64 + j * 16, K1_LDB);
                wmma::load_matrix_sync(bl[j], bsl + kk * K1_LDB + wc * 64 + j * 16, K1_LDB);
            }
#pragma unroll
            for (int j = 0; j < 4; j++)
#pragma unroll
                for (int i = 0; i < 2; i++)
                    wmma::mma_sync(c[i][j], ah[i], bh[j], c[i][j]);
#pragma unroll
            for (int j = 0; j < 4; j++)
#pragma unroll
                for (int i = 0; i < 2; i++)
                    wmma::mma_sync(c[i][j], ah[i], bl[j], c[i][j]);
#pragma unroll
            for (int j = 0; j < 4; j++)
#pragma unroll
                for (int i = 0; i < 2; i++)
                    wmma::mma_sync(c[i][j], al[i], bh[j], c[i][j]);
        }
        __syncthreads();
    }

    a_sh[tid] = an[(size_t)ph * 2 * NHID + tid];
#pragma unroll
    for (int i = 0; i < 2; i++)
#pragma unroll
        for (int j = 0; j < 4; j++)
            wmma::store_matrix_sync(csh + (wr * 32 + i * 16) * K1_LDC + wc * 64 + j * 16,
                                    c[i][j], K1_LDC, wmma::mem_row_major);
    __syncthreads();

    {
        int r = tid & 127, hf = tid >> 7;
        float ps = 0.f, pd = 0.f;
        const float* row = csh + r * K1_LDC + hf * 64;
#pragma unroll
        for (int i = 0; i < 64; i++) {
            float v = row[i];
            ps += v * a_sh[hf * 64 + i];
            pd += v * a_sh[NHID + hf * 64 + i];
        }
        red_s[hf * 128 + r] = ps;
        red_d[hf * 128 + r] = pd;
    }

    // hT fp16 hi/lo
    {
        int d = tid & 127, hf = tid >> 7;
        __half* dstH = g_hThi + ((size_t)ph * NHID + d) * NN + row0 + hf * 64;
        __half* dstL = g_hTlo + ((size_t)ph * NHID + d) * NN + row0 + hf * 64;
#pragma unroll
        for (int i = 0; i < 64; i += 4) {
            float v0 = csh[(hf * 64 + i    ) * K1_LDC + d];
            float v1 = csh[(hf * 64 + i + 1) * K1_LDC + d];
            float v2 = csh[(hf * 64 + i + 2) * K1_LDC + d];
            float v3 = csh[(hf * 64 + i + 3) * K1_LDC + d];
            __half2 h01 = __floats2half2_rn(v0, v1);
            __half2 h23 = __floats2half2_rn(v2, v3);
            __half2 l01 = __floats2half2_rn(v0 - __half2float(__low2half(h01)),
                                            v1 - __half2float(__high2half(h01)));
            __half2 l23 = __floats2half2_rn(v2 - __half2float(__low2half(h23)),
                                            v3 - __half2float(__high2half(h23)));
            *(uint2*)(dstH + i) = make_uint2(h2u(h01), h2u(h23));
            *(uint2*)(dstL + i) = make_uint2(h2u(l01), h2u(l23));
        }
    }
    __syncthreads();
    if (tid < 128) {
        float s = red_s[tid] + red_s[128 + tid];
        float d = red_d[tid] + red_d[128 + tid];
        int idx = ph * NN + row0 + tid;
        g_sE4[idx] = make_float4(expf(s), expf(ALPHA * s), expf(-s), s);
        g_dE2[idx] = make_float2(expf(d), expf(ALPHA * d));
        // per-ph max of d (warp reduce, lane0 atomic)
        float dm = d;
#pragma unroll
        for (int off = 16; off; off >>= 1)
            dm = fmaxf(dm, __shfl_xor_sync(0xffffffffu, dm, off));
        if ((tid & 31) == 0) atomicMaxFloat(&g_maxd[ph], dm);
    }
}

// ---------------- k3: fp16 2-product attention, 4+4 warps, 2 stages, 2 CTA/SM -
// stage (46080 B): A @0 (64x72 half), Bh @9216 (128x72), Bl @27648.
// 2 stages = 92160. dE 2x512 @92160; rowsum 2x64 @93184; mbar @93696.
#define LDA      72
#define LDC      132
#define NSTAGE   2
#define ST_STRIDE 46080
#define OFF_SBH  9216
#define OFF_SBL  27648
#define OFF_DE   92160
#define OFF_ROW  93184
#define OFF_MBAR 93696
#define K3_SMEM_BYTES 94208

__global__ __launch_bounds__(256, 2) void k3_attn_wmma() {
    extern __shared__ char sm[];
    float*  csh  = (float*)(sm);
    float*  rsb  = (float*)(sm + OFF_ROW);
    uint32_t sbase = smem_u32(sm);
    uint32_t mbar = sbase + OFF_MBAR;

    int ph   = blockIdx.y;
    int p    = ph >> 2, head = ph & 3;
    int row0 = blockIdx.x * 64;
    int tid  = threadIdx.x;

    if (tid == 0) {
#pragma unroll
        for (int s = 0; s < NSTAGE; s++) {
            MBAR_INIT(mbar + s * 8, 128);        // full
            MBAR_INIT(mbar + 16 + s * 8, 128);   // empty
        }
    }
    __syncthreads();

    wmma::fragment<wmma::accumulator, 16, 16, 16, float> c[2][4];

    if (tid < 128) {
        // ===== PRODUCER: B cp.async (1 d-row/thread) + A-gen (2 thr/row, fp16) =====
        int r    = tid >> 1;
        int half = tid & 1;
        float4 sE = g_sE4[ph * NN + row0 + r];
        float scale = fminf(1.f, expf(-(sE.w + g_maxd[ph])));
        const float Es_r = sE.x * scale, Eas_r = sE.y * scale, En_r = sE.z;
        float rs_local = 0.f;
        uint32_t phE[NSTAGE] = {0, 0};

        for (int chk = 0; chk < 32; chk++) {
            int s = chk & 1;
            int m0 = chk * 64;
            if (chk >= NSTAGE) { MBAR_WAIT(mbar + 16 + s * 8, phE[s]); phE[s] ^= 1; }

            {   // B tile: one d-row per thread, 8x16B hi + 8x16B lo
                const char* srcH = (const char*)(g_hThi + ((size_t)ph * NHID + tid) * NN + m0);
                const char* srcL = (const char*)(g_hTlo + ((size_t)ph * NHID + tid) * NN + m0);
                uint32_t dstH = sbase + s * ST_STRIDE + OFF_SBH + tid * (LDA * 2);
                uint32_t dstL = sbase + s * ST_STRIDE + OFF_SBL + tid * (LDA * 2);
#pragma unroll
                for (int k = 0; k < 8; k++) {
                    CP_ASYNC16(dstH + k * 16, srcH + k * 16);
                    CP_ASYNC16(dstL + k * 16, srcL + k * 16);
                }
                CP_COMMIT();
            }
            float2* dEs = (float2*)(sm + OFF_DE + s * 512);
            if (tid < 64) dEs[tid] = g_dE2[ph * NN + m0 + tid];
            asm volatile("bar.sync 1, 128;" ::: "memory");

            {   // A tile: row r, m in [m0+half*32, +32), single fp16
                __half* a_ = (__half*)(sm + s * ST_STRIDE) + r * LDA + half * 32;
                uint32_t mw = g_maskN[((size_t)p * NN + row0 + r) * 64 + chk * 2 + half];
#pragma unroll
                for (int g4 = 0; g4 < 4; g4++) {
                    uint32_t hw[4];
#pragma unroll
                    for (int jj = 0; jj < 4; jj++) {
                        float2 q0 = dEs[half * 32 + g4 * 8 + 2*jj];
                        float2 q1 = dEs[half * 32 + g4 * 8 + 2*jj + 1];
                        float w0 = (q0.x > En_r) ? (Es_r * q0.x) : (Eas_r * q0.y);
                        float w1 = (q1.x > En_r) ? (Es_r * q1.x) : (Eas_r * q1.y);
                        w0 = ((mw >> (g4 * 8 + 2*jj))     & 1u) ? w0 : 0.f;
                        w1 = ((mw >> (g4 * 8 + 2*jj + 1)) & 1u) ? w1 : 0.f;
                        __half2 h2 = __floats2half2_rn(w0, w1);
                        rs_local += __half2float(__low2half(h2)) + __half2float(__high2half(h2));
                        hw[jj] = h2u(h2);
                    }
                    *(uint4*)(a_ + g4 * 8) = make_uint4(hw[0], hw[1], hw[2], hw[3]);
                }
            }
            CP_WAIT0();
            MBAR_ARRIVE(mbar + s * 8);
        }
        rsb[half * 64 + r] = rs_local;
    } else {
        // ===== CONSUMER (4 warps, each 32x64 of C): 2-product fp16 MMA =====
        int cw = (tid >> 5) - 4;
        int wr = cw >> 1;
        int wc = cw & 1;
        uint32_t phF[NSTAGE] = {0, 0};

#pragma unroll
        for (int i = 0; i < 2; i++)
#pragma unroll
            for (int j = 0; j < 4; j++) wmma::fill_fragment(c[i][j], 0.f);

        for (int chk = 0; chk < 32; chk++) {
            int s = chk & 1;
            MBAR_WAIT(mbar + s * 8, phF[s]); phF[s] ^= 1;

            __half* as_ = (__half*)(sm + s * ST_STRIDE);
            __half* bsh = (__half*)(sm + s * ST_STRIDE + OFF_SBH);
            __half* bsl = (__half*)(sm + s * ST_STRIDE + OFF_SBL);

#pragma unroll
            for (int ks = 0; ks < 4; ks++) {
                int kk = ks * 16;
                wmma::fragment<wmma::matrix_a, 16, 16, 16, half, wmma::row_major> a[2];
#pragma unroll
                for (int i = 0; i < 2; i++)
                    wmma::load_matrix_sync(a[i], as_ + (wr * 32 + i * 16) * LDA + kk, LDA);
#pragma unroll
                for (int j = 0; j < 4; j++) {
                    wmma::fragment<wmma::matrix_b, 16, 16, 16, half, wmma::col_major> bh, bl;
                    wmma::load_matrix_sync(bh, bsh + (wc * 64 + j * 16) * LDA + kk, LDA);
                    wmma::load_matrix_sync(bl, bsl + (wc * 64 + j * 16) * LDA + kk, LDA);
#pragma unroll
                    for (int i = 0; i < 2; i++) {
                        wmma::mma_sync(c[i][j], a[i], bh, c[i][j]);
                        wmma::mma_sync(c[i][j], a[i], bl, c[i][j]);
                    }
                }
            }
            MBAR_ARRIVE(mbar + 16 + s * 8);
        }
    }

    __syncthreads();
    if (tid >= 128) {
        int cw = (tid >> 5) - 4;
        int wr = cw >> 1, wc = cw & 1;
#pragma unroll
        for (int i = 0; i < 2; i++)
#pragma unroll
            for (int j = 0; j < 4; j++)
                wmma::store_matrix_sync(csh + (wr * 32 + i * 16) * LDC + wc * 64 + j * 16,
                                        c[i][j], LDC, wmma::mem_row_major);
    }
    __syncthreads();

    if (tid < 128) {
        int rr  = tid & 63;
        int chf = tid >> 6;
        float rsum = rsb[rr] + rsb[64 + rr];
        float inv = (rsum > 0.f) ? (1.f / rsum) : 0.f;
        const float* src = csh + rr * LDC + chf * 64;
        float* dst = g_m + ((size_t)p * NN + row0 + rr) * (NHEADS * NHID) + head * NHID + chf * 64;
#pragma unroll
        for (int cc = 0; cc < 64; cc += 4) {
            float f0 = src[cc]   * inv;
            float f1 = src[cc+1] * inv;
            float f2 = src[cc+2] * inv;
            float f3 = src[cc+3] * inv;
            f0 = (f0 > 0.f) ? f0 : expm1f(f0);
            f1 = (f1 > 0.f) ? f1 : expm1f(f1);
            f2 = (f2 > 0.f) ? f2 : expm1f(f2);
            f3 = (f3 > 0.f) ? f3 : expm1f(f3);
            *(float4*)(dst + cc) = make_float4(f0, f1, f2, f3);
        }
    }
}

// ---------------- k4: semantic scores ----------------
__global__ __launch_bounds__(256) void k4_sem(const float* __restrict__ Wsem,
                                              const float* __restrict__ bsem,
                                              const float* __restrict__ qsem) {
    __shared__ float msh[32][65];
    __shared__ float wsh[64 * 128];
    __shared__ float red[8];
    int row0 = blockIdx.x * 32;
    int pidx = row0 / NN;
    int tid = threadIdx.x;
    int rg = tid >> 5;
    int cg = tid & 31;

    float acc[4][4];
#pragma unroll
    for (int r = 0; r < 4; r++)
#pragma unroll
        for (int c = 0; c < 4; c++) acc[r][c] = 0.f;

    for (int k0 = 0; k0 < 512; k0 += 64) {
        for (int i = tid; i < 32 * 64; i += 256)
            msh[i >> 6][i & 63] = g_m[(size_t)(row0 + (i >> 6)) * 512 + k0 + (i & 63)];
        for (int i = tid * 4; i < 64 * 128; i += 1024)
            *(float4*)&wsh[i] = *(const float4*)&Wsem[(size_t)k0 * 128 + i];
        __syncthreads();
#pragma unroll
        for (int k = 0; k < 64; k++) {
            float mv[4];
#pragma unroll
            for (int r = 0; r < 4; r++) mv[r] = msh[rg * 4 + r][k];
            float4 wv = *(float4*)&wsh[k * 128 + cg * 4];
            float wva[4] = {wv.x, wv.y, wv.z, wv.w};
#pragma unroll
            for (int r = 0; r < 4; r++)
#pragma unroll
                for (int c = 0; c < 4; c++) acc[r][c] += mv[r] * wva[c];
        }
        __syncthreads();
    }
    float part = 0.f;
#pragma unroll
    for (int c = 0; c < 4; c++) {
        int col = cg * 4 + c;
        float b = bsem[col], q = qsem[col];
#pragma unroll
        for (int r = 0; r < 4; r++)
            part += tanhf(acc[r][c] + b) * q;
    }
#pragma unroll
    for (int off = 16; off; off >>= 1)
        part += __shfl_xor_sync(0xffffffffu, part, off);
    if ((tid & 31) == 0) red[tid >> 5] = part;
    __syncthreads();
    if (tid == 0) {
        float tot = 0.f;
#pragma unroll
        for (int i = 0; i < 8; i++) tot += red[i];
        atomicAdd(&g_scores[pidx], tot);
    }
}

// ---------------- k6 ----------------
__global__ __launch_bounds__(256) void k6_out(float* __restrict__ out) {
    __shared__ float w[NP];
    if (threadIdx.x == 0) {
        float s0 = g_scores[0] * (1.f / NN);
        float s1 = g_scores[1] * (1.f / NN);
        float s2 = g_scores[2] * (1.f / NN);
        float mx = fmaxf(s0, fmaxf(s1, s2));
        float e0 = expf(s0 - mx), e1 = expf(s1 - mx), e2 = expf(s2 - mx);
        float inv = 1.f / (e0 + e1 + e2);
        w[0] = e0 * inv; w[1] = e1 * inv; w[2] = e2 * inv;
    }
    __syncthreads();
    size_t i = (size_t)blockIdx.x * blockDim.x + threadIdx.x;
    const size_t stride = (size_t)NN * 512;
    out[i] = w[0] * g_m[i] + w[1] * g_m[stride + i] + w[2] * g_m[2 * stride + i];
}

// ---------------- launch ----------------
extern "C" void kernel_launch(void* const* d_in, const int* in_sizes, int n_in,
                              void* d_out, int out_size) {
    const float* x    = (const float*)d_in[0];
    const float* adjs = (const float*)d_in[1];
    const float* Wn   = (const float*)d_in[2];
    const float* an   = (const float*)d_in[3];
    const float* Wsem = (const float*)d_in[4];
    const float* bsem = (const float*)d_in[5];
    const float* qsem = (const float*)d_in[6];
    float* out = (float*)d_out;

    cudaFuncSetAttribute(k3_attn_wmma, cudaFuncAttributeMaxDynamicSharedMemorySize, K3_SMEM_BYTES);
    cudaFuncSetAttribute(k1_node_wmma, cudaFuncAttributeMaxDynamicSharedMemorySize, K1_SMEM_BYTES);

    k0_init<<<1, 32>>>();
    k_prep<<<PACK_BLOCKS, 256>>>(x, Wn, adjs);
    k1_node_wmma<<<dim3(NN / 128, PH), 256, K1_SMEM_BYTES>>>(an);
    k3_attn_wmma<<<dim3(NN / 64, PH), 256, K3_SMEM_BYTES>>>();   // profiled slot
    k4_sem<<<(NP * NN) / 32, 256>>>(Wsem, bsem, qsem);
    k6_out<<<(NN * 512) / 256, 256>>>(out);
}

// round 17
// speedup vs baseline: 1.5124x; 1.2716x over previous
#include <cuda_runtime.h>
#include <cuda_bf16.h>
#include <cuda_fp16.h>
#include <mma.h>
#include <math.h>
#include <stdint.h>
#include <string.h>

using namespace nvcuda;

#define NN     2048
#define NFEAT  512
#define NHID   128
#define NHEADS 4
#define NP     3
#define PH     (NP*NHEADS)
#define ALPHA  0.2f

// ---------------- device scratch ----------------
__device__ float g_m[NP * NN * (NHEADS*NHID)];
__device__ __align__(16) __half g_hT[PH * NHID * NN];     // hT fp16
__device__ __align__(16) __nv_bfloat16 g_xhi[NN * NFEAT];
__device__ __align__(16) __nv_bfloat16 g_xlo[NN * NFEAT];
__device__ __align__(16) __nv_bfloat16 g_Whi[PH * NFEAT * NHID];
__device__ __align__(16) __nv_bfloat16 g_Wlo[PH * NFEAT * NHID];
__device__ float4  g_sE4[PH * NN];     // (e^s, e^{as}, e^{-s}, s)
__device__ float2  g_dE2[PH * NN];     // (e^d, e^{ad})
__device__ float   g_maxd[PH];
__device__ uint32_t g_maskN[NP * NN * (NN/32)];
__device__ float g_scores[NP];

static __device__ __forceinline__ uint32_t b2u(__nv_bfloat162 h) {
    uint32_t u; memcpy(&u, &h, 4); return u;
}
static __device__ __forceinline__ uint32_t h2u(__half2 h) {
    uint32_t u; memcpy(&u, &h, 4); return u;
}
static __device__ __forceinline__ uint32_t smem_u32(const void* p) {
    uint32_t a;
    asm("{ .reg .u64 t; cvta.to.shared.u64 t, %1; cvt.u32.u64 %0, t; }" : "=r"(a) : "l"(p));
    return a;
}
static __device__ __forceinline__ void atomicMaxFloat(float* addr, float val) {
    int* ia = (int*)addr;
    int old = *ia;
    while (val > __int_as_float(old)) {
        int assumed = old;
        old = atomicCAS(ia, assumed, __float_as_int(val));
        if (old == assumed) break;
    }
}
#define MBAR_INIT(a, c)  asm volatile("mbarrier.init.shared.b64 [%0], %1;" :: "r"((uint32_t)(a)), "r"((uint32_t)(c)) : "memory")
#define MBAR_ARRIVE(a)   asm volatile("mbarrier.arrive.shared.b64 _, [%0];" :: "r"((uint32_t)(a)) : "memory")
#define MBAR_WAIT(a, par) do { \
    uint32_t _m = (uint32_t)(a), _p = (uint32_t)(par), _d; \
    asm volatile("{\n\t.reg .pred p;\n\tmbarrier.try_wait.parity.acquire.cta.shared::cta.b64 p, [%1], %2;\n\tselp.b32 %0, 1, 0, p;\n\t}" \
                 : "=r"(_d) : "r"(_m), "r"(_p) : "memory"); \
    if (!_d) { \
        asm volatile("{\n\t.reg .pred P1;\n\tWL_%=:\n\tmbarrier.try_wait.parity.acquire.cta.shared::cta.b64 P1, [%0], %1, 0x989680;\n\t@P1 bra.uni WD_%=;\n\tbra.uni WL_%=;\n\tWD_%=:\n\t}" \
                     :: "r"(_m), "r"(_p) : "memory"); \
    } \
} while (0)
#define CP_ASYNC16(smem, gptr) \
    asm volatile("cp.async.cg.shared.global [%0], [%1], 16;" :: "r"((uint32_t)(smem)), "l"(gptr) : "memory")
#define CP_COMMIT()  asm volatile("cp.async.commit_group;" ::: "memory")
#define CP_WAIT0()   asm volatile("cp.async.wait_group 0;" ::: "memory")
#define CP_WAIT1()   asm volatile("cp.async.wait_group 1;" ::: "memory")

// ---------------- k0 ----------------
__global__ void k0_init() {
    if (threadIdx.x < NP) g_scores[threadIdx.x] = 0.f;
    if (threadIdx.x < PH) g_maxd[threadIdx.x] = -1e30f;
}

// ---------------- k_prep: fused split + pack ----------
#define NXE (NN * NFEAT)
#define NWE (PH * NFEAT * NHID)
#define SPLIT_BLOCKS ((NXE + NWE + 255) / 256)
#define PACK_BLOCKS  (NP * NN * 64 / 8)
__global__ __launch_bounds__(256) void k_prep(const float* __restrict__ x,
                                              const float* __restrict__ Wn,
                                              const float* __restrict__ adjs) {
    {
        int g = blockIdx.x * 8 + (threadIdx.x >> 5);
        int lane = threadIdx.x & 31;
        float v = adjs[(size_t)g * 32 + lane];
        uint32_t b = __ballot_sync(0xffffffffu, v > 0.f);
        if (lane == 0) g_maskN[g] = b;
    }
    if (blockIdx.x < SPLIT_BLOCKS) {
        int i = blockIdx.x * 256 + threadIdx.x;
        if (i < NXE) {
            float v = x[i];
            __nv_bfloat16 h = __float2bfloat16_rn(v);
            g_xhi[i] = h;
            g_xlo[i] = __float2bfloat16_rn(v - __bfloat162float(h));
        }
        int j = i - NXE;
        if (j >= 0 && j < NWE) {
            float v = Wn[j];
            __nv_bfloat16 h = __float2bfloat16_rn(v);
            g_Whi[j] = h;
            g_Wlo[j] = __float2bfloat16_rn(v - __bfloat162float(h));
        }
    }
}

// ---------------- k1: 2-stage K=32 pipelined WMMA node GEMM, 2 CTA/SM ---------
#define K1_LDA   40
#define K1_LDB   136
#define K1_LDC   132
#define K1_ST    37888
#define K1_OAL   10240
#define K1_OBH   20480
#define K1_OBL   29184
#define K1_OAN   75776
#define K1_ORS   76800
#define K1_ORD   77824
#define K1_SMEM_BYTES 78848

__global__ __launch_bounds__(256, 2) void k1_node_wmma(const float* __restrict__ an) {
    extern __shared__ char sm[];
    uint32_t sbase = smem_u32(sm);
    float* csh   = (float*)(sm);
    float* a_sh  = (float*)(sm + K1_OAN);
    float* red_s = (float*)(sm + K1_ORS);
    float* red_d = (float*)(sm + K1_ORD);

    int ph   = blockIdx.y;
    int row0 = blockIdx.x * 128;
    int tid  = threadIdx.x;
    int warp = tid >> 5;
    int wr   = warp >> 1;
    int wc   = warp & 1;

    int rA = tid >> 1, hA = tid & 1;
    int rB = tid >> 3, qB = tid & 7;

    const char* xsrcH = (const char*)(g_xhi + (size_t)(row0 + rA) * NFEAT + hA * 16);
    const char* xsrcL = (const char*)(g_xlo + (size_t)(row0 + rA) * NFEAT + hA * 16);
    const char* wsrcH = (const char*)(g_Whi + (size_t)ph * NFEAT * NHID + (size_t)rB * NHID + qB * 16);
    const char* wsrcL = (const char*)(g_Wlo + (size_t)ph * NFEAT * NHID + (size_t)rB * NHID + qB * 16);
    uint32_t adstH = sbase + rA * (K1_LDA * 2) + hA * 32;
    uint32_t adstL = adstH + K1_OAL;
    uint32_t bdstH = sbase + K1_OBH + rB * (K1_LDB * 2) + qB * 32;
    uint32_t bdstL = bdstH + (K1_OBL - K1_OBH);

#define K1_ISSUE(c) do { \
    uint32_t _sb = ((c) & 1) * K1_ST; size_t _ko = (size_t)(c) * 32; \
    const char* _xh = xsrcH + _ko * 2; const char* _xl = xsrcL + _ko * 2; \
    const char* _wh = wsrcH + _ko * NHID * 2; const char* _wl = wsrcL + _ko * NHID * 2; \
    CP_ASYNC16(adstH + _sb,      _xh); CP_ASYNC16(adstH + _sb + 16, _xh + 16); \
    CP_ASYNC16(adstL + _sb,      _xl); CP_ASYNC16(adstL + _sb + 16, _xl + 16); \
    CP_ASYNC16(bdstH + _sb,      _wh); CP_ASYNC16(bdstH + _sb + 16, _wh + 16); \
    CP_ASYNC16(bdstL + _sb,      _wl); CP_ASYNC16(bdstL + _sb + 16, _wl + 16); \
    CP_COMMIT(); \
} while (0)

    wmma::fragment<wmma::accumulator, 16, 16, 16, float> c[2][4];
#pragma unroll
    for (int i = 0; i < 2; i++)
#pragma unroll
        for (int j = 0; j < 4; j++) wmma::fill_fragment(c[i][j], 0.f);

    K1_ISSUE(0);

    for (int ch = 0; ch < 16; ch++) {
        int s = ch & 1;
        if (ch + 1 < 16) { K1_ISSUE(ch + 1); CP_WAIT1(); } else { CP_WAIT0(); }
        __syncthreads();

        __nv_bfloat16* ash = (__nv_bfloat16*)(sm + s * K1_ST);
        __nv_bfloat16* asl = (__nv_bfloat16*)(sm + s * K1_ST + K1_OAL);
        __nv_bfloat16* bsh = (__nv_bfloat16*)(sm + s * K1_ST + K1_OBH);
        __nv_bfloat16* bsl = (__nv_bfloat16*)(sm + s * K1_ST + K1_OBL);

#pragma unroll
        for (int ks = 0; ks < 2; ks++) {
            int kk = ks * 16;
            wmma::fragment<wmma::matrix_a, 16, 16, 16, __nv_bfloat16, wmma::row_major> ah[2], al[2];
            wmma::fragment<wmma::matrix_b, 16, 16, 16, __nv_bfloat16, wmma::row_major> bh[4], bl[4];
#pragma unroll
            for (int i = 0; i < 2; i++) {
                wmma::load_matrix_sync(ah[i], ash + (wr * 32 + i * 16) * K1_LDA + kk, K1_LDA);
                wmma::load_matrix_sync(al[i], asl + (wr * 32 + i * 16) * K1_LDA + kk, K1_LDA);
            }
#pragma unroll
            for (int j = 0; j < 4; j++) {
                wmma::load_matrix_sync(bh[j], bsh + kk * K1_LDB + wc * 64 + j * 16, K1_LDB);
                wmma::load_matrix_sync(bl[j], bsl + kk * K1_LDB + wc * 64 + j * 16, K1_LDB);
            }
#pragma unroll
            for (int j = 0; j < 4; j++)
#pragma unroll
                for (int i = 0; i < 2; i++)
                    wmma::mma_sync(c[i][j], ah[i], bh[j], c[i][j]);
#pragma unroll
            for (int j = 0; j < 4; j++)
#pragma unroll
                for (int i = 0; i < 2; i++)
                    wmma::mma_sync(c[i][j], ah[i], bl[j], c[i][j]);
#pragma unroll
            for (int j = 0; j < 4; j++)
#pragma unroll
                for (int i = 0; i < 2; i++)
                    wmma::mma_sync(c[i][j], al[i], bh[j], c[i][j]);
        }
        __syncthreads();
    }

    a_sh[tid] = an[(size_t)ph * 2 * NHID + tid];
#pragma unroll
    for (int i = 0; i < 2; i++)
#pragma unroll
        for (int j = 0; j < 4; j++)
            wmma::store_matrix_sync(csh + (wr * 32 + i * 16) * K1_LDC + wc * 64 + j * 16,
                                    c[i][j], K1_LDC, wmma::mem_row_major);
    __syncthreads();

    {
        int r = tid & 127, hf = tid >> 7;
        float ps = 0.f, pd = 0.f;
        const float* row = csh + r * K1_LDC + hf * 64;
#pragma unroll
        for (int i = 0; i < 64; i++) {
            float v = row[i];
            ps += v * a_sh[hf * 64 + i];
            pd += v * a_sh[NHID + hf * 64 + i];
        }
        red_s[hf * 128 + r] = ps;
        red_d[hf * 128 + r] = pd;
    }

    // hT fp16 (single)
    {
        int d = tid & 127, hf = tid >> 7;
        __half* dstH = g_hT + ((size_t)ph * NHID + d) * NN + row0 + hf * 64;
#pragma unroll
        for (int i = 0; i < 64; i += 4) {
            float v0 = csh[(hf * 64 + i    ) * K1_LDC + d];
            float v1 = csh[(hf * 64 + i + 1) * K1_LDC + d];
            float v2 = csh[(hf * 64 + i + 2) * K1_LDC + d];
            float v3 = csh[(hf * 64 + i + 3) * K1_LDC + d];
            __half2 h01 = __floats2half2_rn(v0, v1);
            __half2 h23 = __floats2half2_rn(v2, v3);
            *(uint2*)(dstH + i) = make_uint2(h2u(h01), h2u(h23));
        }
    }
    __syncthreads();
    if (tid < 128) {
        float s = red_s[tid] + red_s[128 + tid];
        float d = red_d[tid] + red_d[128 + tid];
        int idx = ph * NN + row0 + tid;
        g_sE4[idx] = make_float4(expf(s), expf(ALPHA * s), expf(-s), s);
        g_dE2[idx] = make_float2(expf(d), expf(ALPHA * d));
        float dm = d;
#pragma unroll
        for (int off = 16; off; off >>= 1)
            dm = fmaxf(dm, __shfl_xor_sync(0xffffffffu, dm, off));
        if ((tid & 31) == 0) atomicMaxFloat(&g_maxd[ph], dm);
    }
}

// ---------------- k3: fp16 1-product attention, 4+4 warps, 2 stages, 2 CTA/SM -
// stage (27648 B): A @0 (64x72 half), B @9216 (128x72 half).
// 2 stages = 55296. dE 2x512 @55296; rowsum 2x64 @56320; mbar @56832.
// C tile (64x132 f32 = 33792) aliases stages (dead by epilogue).
#define LDA      72
#define LDC      132
#define NSTAGE   2
#define ST_STRIDE 27648
#define OFF_SB   9216
#define OFF_DE   55296
#define OFF_ROW  56320
#define OFF_MBAR 56832
#define K3_SMEM_BYTES 57344

__global__ __launch_bounds__(256, 2) void k3_attn_wmma() {
    extern __shared__ char sm[];
    float*  csh  = (float*)(sm);
    float*  rsb  = (float*)(sm + OFF_ROW);
    uint32_t sbase = smem_u32(sm);
    uint32_t mbar = sbase + OFF_MBAR;

    int ph   = blockIdx.y;
    int p    = ph >> 2, head = ph & 3;
    int row0 = blockIdx.x * 64;
    int tid  = threadIdx.x;

    if (tid == 0) {
#pragma unroll
        for (int s = 0; s < NSTAGE; s++) {
            MBAR_INIT(mbar + s * 8, 128);        // full
            MBAR_INIT(mbar + 16 + s * 8, 128);   // empty
        }
    }
    __syncthreads();

    wmma::fragment<wmma::accumulator, 16, 16, 16, float> c[2][4];

    if (tid < 128) {
        // ===== PRODUCER: B cp.async (1 d-row/thread) + A-gen (2 thr/row, fp16) =====
        int r    = tid >> 1;
        int half = tid & 1;
        float4 sE = g_sE4[ph * NN + row0 + r];
        float scale = fminf(1.f, expf(-(sE.w + g_maxd[ph])));
        const float Es_r = sE.x * scale, Eas_r = sE.y * scale, En_r = sE.z;
        float rs_local = 0.f;
        uint32_t phE[NSTAGE] = {0, 0};

        for (int chk = 0; chk < 32; chk++) {
            int s = chk & 1;
            int m0 = chk * 64;
            if (chk >= NSTAGE) { MBAR_WAIT(mbar + 16 + s * 8, phE[s]); phE[s] ^= 1; }

            {   // B tile: one d-row per thread, 8x16B
                const char* src = (const char*)(g_hT + ((size_t)ph * NHID + tid) * NN + m0);
                uint32_t dst = sbase + s * ST_STRIDE + OFF_SB + tid * (LDA * 2);
#pragma unroll
                for (int k = 0; k < 8; k++) CP_ASYNC16(dst + k * 16, src + k * 16);
                CP_COMMIT();
            }
            float2* dEs = (float2*)(sm + OFF_DE + s * 512);
            if (tid < 64) dEs[tid] = g_dE2[ph * NN + m0 + tid];
            asm volatile("bar.sync 1, 128;" ::: "memory");

            {   // A tile: row r, m in [m0+half*32, +32), fp16
                __half* a_ = (__half*)(sm + s * ST_STRIDE) + r * LDA + half * 32;
                uint32_t mw = g_maskN[((size_t)p * NN + row0 + r) * 64 + chk * 2 + half];
#pragma unroll
                for (int g4 = 0; g4 < 4; g4++) {
                    uint32_t hw[4];
#pragma unroll
                    for (int jj = 0; jj < 4; jj++) {
                        float2 q0 = dEs[half * 32 + g4 * 8 + 2*jj];
                        float2 q1 = dEs[half * 32 + g4 * 8 + 2*jj + 1];
                        float w0 = (q0.x > En_r) ? (Es_r * q0.x) : (Eas_r * q0.y);
                        float w1 = (q1.x > En_r) ? (Es_r * q1.x) : (Eas_r * q1.y);
                        w0 = ((mw >> (g4 * 8 + 2*jj))     & 1u) ? w0 : 0.f;
                        w1 = ((mw >> (g4 * 8 + 2*jj + 1)) & 1u) ? w1 : 0.f;
                        __half2 h2 = __floats2half2_rn(w0, w1);
                        rs_local += __half2float(__low2half(h2)) + __half2float(__high2half(h2));
                        hw[jj] = h2u(h2);
                    }
                    *(uint4*)(a_ + g4 * 8) = make_uint4(hw[0], hw[1], hw[2], hw[3]);
                }
            }
            CP_WAIT0();
            MBAR_ARRIVE(mbar + s * 8);
        }
        rsb[half * 64 + r] = rs_local;
    } else {
        // ===== CONSUMER (4 warps, each 32x64 of C): single-product fp16 MMA =====
        int cw = (tid >> 5) - 4;
        int wr = cw >> 1;
        int wc = cw & 1;
        uint32_t phF[NSTAGE] = {0, 0};

#pragma unroll
        for (int i = 0; i < 2; i++)
#pragma unroll
            for (int j = 0; j < 4; j++) wmma::fill_fragment(c[i][j], 0.f);

        for (int chk = 0; chk < 32; chk++) {
            int s = chk & 1;
            MBAR_WAIT(mbar + s * 8, phF[s]); phF[s] ^= 1;

            __half* as_ = (__half*)(sm + s * ST_STRIDE);
            __half* bs_ = (__half*)(sm + s * ST_STRIDE + OFF_SB);

#pragma unroll
            for (int ks = 0; ks < 4; ks++) {
                int kk = ks * 16;
                wmma::fragment<wmma::matrix_a, 16, 16, 16, half, wmma::row_major> a[2];
#pragma unroll
                for (int i = 0; i < 2; i++)
                    wmma::load_matrix_sync(a[i], as_ + (wr * 32 + i * 16) * LDA + kk, LDA);
#pragma unroll
                for (int j = 0; j < 4; j++) {
                    wmma::fragment<wmma::matrix_b, 16, 16, 16, half, wmma::col_major> b;
                    wmma::load_matrix_sync(b, bs_ + (wc * 64 + j * 16) * LDA + kk, LDA);
#pragma unroll
                    for (int i = 0; i < 2; i++)
                        wmma::mma_sync(c[i][j], a[i], b, c[i][j]);
                }
            }
            MBAR_ARRIVE(mbar + 16 + s * 8);
        }
    }

    __syncthreads();
    if (tid >= 128) {
        int cw = (tid >> 5) - 4;
        int wr = cw >> 1, wc = cw & 1;
#pragma unroll
        for (int i = 0; i < 2; i++)
#pragma unroll
            for (int j = 0; j < 4; j++)
                wmma::store_matrix_sync(csh + (wr * 32 + i * 16) * LDC + wc * 64 + j * 16,
                                        c[i][j], LDC, wmma::mem_row_major);
    }
    __syncthreads();

    if (tid < 128) {
        int rr  = tid & 63;
        int chf = tid >> 6;
        float rsum = rsb[rr] + rsb[64 + rr];
        float inv = (rsum > 0.f) ? (1.f / rsum) : 0.f;
        const float* src = csh + rr * LDC + chf * 64;
        float* dst = g_m + ((size_t)p * NN + row0 + rr) * (NHEADS * NHID) + head * NHID + chf * 64;
#pragma unroll
        for (int cc = 0; cc < 64; cc += 4) {
            float f0 = src[cc]   * inv;
            float f1 = src[cc+1] * inv;
            float f2 = src[cc+2] * inv;
            float f3 = src[cc+3] * inv;
            f0 = (f0 > 0.f) ? f0 : expm1f(f0);
            f1 = (f1 > 0.f) ? f1 : expm1f(f1);
            f2 = (f2 > 0.f) ? f2 : expm1f(f2);
            f3 = (f3 > 0.f) ? f3 : expm1f(f3);
            *(float4*)(dst + cc) = make_float4(f0, f1, f2, f3);
        }
    }
}

// ---------------- k4: semantic scores ----------------
__global__ __launch_bounds__(256) void k4_sem(const float* __restrict__ Wsem,
                                              const float* __restrict__ bsem,
                                              const float* __restrict__ qsem) {
    __shared__ float msh[32][65];
    __shared__ float wsh[64 * 128];
    __shared__ float red[8];
    int row0 = blockIdx.x * 32;
    int pidx = row0 / NN;
    int tid = threadIdx.x;
    int rg = tid >> 5;
    int cg = tid & 31;

    float acc[4][4];
#pragma unroll
    for (int r = 0; r < 4; r++)
#pragma unroll
        for (int c = 0; c < 4; c++) acc[r][c] = 0.f;

    for (int k0 = 0; k0 < 512; k0 += 64) {
        for (int i = tid; i < 32 * 64; i += 256)
            msh[i >> 6][i & 63] = g_m[(size_t)(row0 + (i >> 6)) * 512 + k0 + (i & 63)];
        for (int i = tid * 4; i < 64 * 128; i += 1024)
            *(float4*)&wsh[i] = *(const float4*)&Wsem[(size_t)k0 * 128 + i];
        __syncthreads();
#pragma unroll
        for (int k = 0; k < 64; k++) {
            float mv[4];
#pragma unroll
            for (int r = 0; r < 4; r++) mv[r] = msh[rg * 4 + r][k];
            float4 wv = *(float4*)&wsh[k * 128 + cg * 4];
            float wva[4] = {wv.x, wv.y, wv.z, wv.w};
#pragma unroll
            for (int r = 0; r < 4; r++)
#pragma unroll
                for (int c = 0; c < 4; c++) acc[r][c] += mv[r] * wva[c];
        }
        __syncthreads();
    }
    float part = 0.f;
#pragma unroll
    for (int c = 0; c < 4; c++) {
        int col = cg * 4 + c;
        float b = bsem[col], q = qsem[col];
#pragma unroll
        for (int r = 0; r < 4; r++)
            part += tanhf(acc[r][c] + b) * q;
    }
#pragma unroll
    for (int off = 16; off; off >>= 1)
        part += __shfl_xor_sync(0xffffffffu, part, off);
    if ((tid & 31) == 0) red[tid >> 5] = part;
    __syncthreads();
    if (tid == 0) {
        float tot = 0.f;
#pragma unroll
        for (int i = 0; i < 8; i++) tot += red[i];
        atomicAdd(&g_scores[pidx], tot);
    }
}

// ---------------- k6 ----------------
__global__ __launch_bounds__(256) void k6_out(float* __restrict__ out) {
    __shared__ float w[NP];
    if (threadIdx.x == 0) {
        float s0 = g_scores[0] * (1.f / NN);
        float s1 = g_scores[1] * (1.f / NN);
        float s2 = g_scores[2] * (1.f / NN);
        float mx = fmaxf(s0, fmaxf(s1, s2));
        float e0 = expf(s0 - mx), e1 = expf(s1 - mx), e2 = expf(s2 - mx);
        float inv = 1.f / (e0 + e1 + e2);
        w[0] = e0 * inv; w[1] = e1 * inv; w[2] = e2 * inv;
    }
    __syncthreads();
    size_t i = (size_t)blockIdx.x * blockDim.x + threadIdx.x;
    const size_t stride = (size_t)NN * 512;
    out[i] = w[0] * g_m[i] + w[1] * g_m[stride + i] + w[2] * g_m[2 * stride + i];
}

// ---------------- launch ----------------
extern "C" void kernel_launch(void* const* d_in, const int* in_sizes, int n_in,
                              void* d_out, int out_size) {
    const float* x    = (const float*)d_in[0];
    const float* adjs = (const float*)d_in[1];
    const float* Wn   = (const float*)d_in[2];
    const float* an   = (const float*)d_in[3];
    const float* Wsem = (const float*)d_in[4];
    const float* bsem = (const float*)d_in[5];
    const float* qsem = (const float*)d_in[6];
    float* out = (float*)d_out;

    cudaFuncSetAttribute(k3_attn_wmma, cudaFuncAttributeMaxDynamicSharedMemorySize, K3_SMEM_BYTES);
    cudaFuncSetAttribute(k1_node_wmma, cudaFuncAttributeMaxDynamicSharedMemorySize, K1_SMEM_BYTES);

    k0_init<<<1, 32>>>();
    k_prep<<<PACK_BLOCKS, 256>>>(x, Wn, adjs);
    k1_node_wmma<<<dim3(NN / 128, PH), 256, K1_SMEM_BYTES>>>(an);
    k3_attn_wmma<<<dim3(NN / 64, PH), 256, K3_SMEM_BYTES>>>();   // profiled slot
    k4_sem<<<(NP * NN) / 32, 256>>>(Wsem, bsem, qsem);
    k6_out<<<(NN * 512) / 256, 256>>>(out);
}